// round 2
// baseline (speedup 1.0000x reference)
#include <cuda_runtime.h>
#include <math.h>

// Problem constants
#define Bq 32
#define Sq 512
#define Dq 1024
#define Hq 1024
#define NG 4096            // 4*H
#define Mq (Bq * Sq)       // 16384

#define NB 128             // persistent CTAs (<=148 SMs, 1/SM -> all resident)
#define NT 256             // threads per CTA in recurrent kernel
#define KB 64              // k-block staged per inner iteration
#define WS_PAD 1028        // padded row stride (floats) for Ws in smem

// Scratch (device globals -- no allocations allowed)
static __device__ float g_Gx[(size_t)Mq * NG];     // input-side gates (both layers reuse)
static __device__ float g_H0[(size_t)Mq * Hq];     // layer-0 hidden outputs, [b*S+t][H]
static __device__ float g_ht[2][2][Hq * Bq];       // [layer][parity][unit*32+batch] transposed h
static __device__ float g_cst[2][Hq * Bq];         // [layer][unit*32+batch] cell state
static __device__ unsigned g_bar[2];               // grid-barrier counters, one per layer

// ---------------------------------------------------------------------------
// Zero recurrent state + barrier counters (every launch: determinism)
// ---------------------------------------------------------------------------
__global__ void k_zero_state() {
    int i = blockIdx.x * blockDim.x + threadIdx.x;
    if (i < Hq * Bq) {
        g_ht[0][0][i] = 0.f; g_ht[0][1][i] = 0.f;
        g_ht[1][0][i] = 0.f; g_ht[1][1][i] = 0.f;
        g_cst[0][i] = 0.f;   g_cst[1][i] = 0.f;
    }
    if (i == 0) { g_bar[0] = 0u; g_bar[1] = 0u; }
}

// ---------------------------------------------------------------------------
// g_Gx[M,4096] = A[M,1024] @ W[4096,1024]^T + b1 + b2
// A_in == nullptr means use g_H0. BM=BN=128, BK=16, 256 thr, 8x8 microtile.
// ---------------------------------------------------------------------------
__global__ __launch_bounds__(256) void k_gemm_bias(
    const float* __restrict__ A_in, const float* __restrict__ W,
    const float* __restrict__ b1, const float* __restrict__ b2)
{
    const float* A = A_in ? A_in : g_H0;
    __shared__ float As[16][128];
    __shared__ float Bs[16][128];

    int tid = threadIdx.x;
    int bm = blockIdx.y * 128;
    int bn = blockIdx.x * 128;
    int ty = tid >> 4;   // 0..15
    int tx = tid & 15;   // 0..15

    float acc[8][8];
#pragma unroll
    for (int i = 0; i < 8; i++)
#pragma unroll
        for (int j = 0; j < 8; j++) acc[i][j] = 0.f;

    const float* Ap = A + (size_t)bm * 1024;
    const float* Wp = W + (size_t)bn * 1024;

    for (int k0 = 0; k0 < 1024; k0 += 16) {
#pragma unroll
        for (int r = 0; r < 2; r++) {
            int id = tid + r * 256;          // 0..511
            int row = id >> 2;               // 0..127
            int k4 = (id & 3) * 4;           // 0,4,8,12
            float4 va = *(const float4*)(Ap + (size_t)row * 1024 + k0 + k4);
            As[k4 + 0][row] = va.x; As[k4 + 1][row] = va.y;
            As[k4 + 2][row] = va.z; As[k4 + 3][row] = va.w;
            float4 vb = *(const float4*)(Wp + (size_t)row * 1024 + k0 + k4);
            Bs[k4 + 0][row] = vb.x; Bs[k4 + 1][row] = vb.y;
            Bs[k4 + 2][row] = vb.z; Bs[k4 + 3][row] = vb.w;
        }
        __syncthreads();

#pragma unroll
        for (int kk = 0; kk < 16; kk++) {
            float ar[8], br[8];
            *(float4*)&ar[0] = *(const float4*)&As[kk][ty * 8];
            *(float4*)&ar[4] = *(const float4*)&As[kk][ty * 8 + 4];
            *(float4*)&br[0] = *(const float4*)&Bs[kk][tx * 8];
            *(float4*)&br[4] = *(const float4*)&Bs[kk][tx * 8 + 4];
#pragma unroll
            for (int i = 0; i < 8; i++)
#pragma unroll
                for (int j = 0; j < 8; j++)
                    acc[i][j] += ar[i] * br[j];
        }
        __syncthreads();
    }

    float bias[8];
#pragma unroll
    for (int j = 0; j < 8; j++) {
        int col = bn + tx * 8 + j;
        bias[j] = b1[col] + b2[col];
    }
#pragma unroll
    for (int i = 0; i < 8; i++) {
        size_t row = (size_t)(bm + ty * 8 + i);
#pragma unroll
        for (int j = 0; j < 8; j++) {
            g_Gx[row * NG + bn + tx * 8 + j] = acc[i][j] + bias[j];
        }
    }
}

// ---------------------------------------------------------------------------
// Persistent recurrent kernel: one launch runs all 512 timesteps of a layer.
// Block bx owns units u0 = bx*8..+7 (32 gate rows), all 32 batches.
// Wh slice (32 rows x 1024) cached in dynamic smem for ALL steps.
// h state transposed in global [unit*32+batch], read via __ldcg (L2-coherent).
// Software grid barrier between steps (all 128 CTAs resident, 1/SM).
// ---------------------------------------------------------------------------
extern __shared__ float s_ws[];   // [32][WS_PAD]

__global__ __launch_bounds__(NT) void k_recur(
    const float* __restrict__ Wh, float* __restrict__ dout, int layer)
{
    __shared__ float Hs[KB][32];   // staged h: [k][batch]
    __shared__ float Gs[32][33];   // recombination: [gate-row][batch]

    int tid = threadIdx.x;
    int u0 = blockIdx.x * 8;

    // ---- load Wh slice once: s_ws[row][k], row = gate*8 + uu ----
    {
        int row = tid >> 3;                 // 0..31
        int k4  = (tid & 7) * 4;            // 0..28
        int jrow = (row >> 3) * Hq + u0 + (row & 7);
        const float* wr = Wh + (size_t)jrow * Hq;
        for (int k = k4; k < Hq; k += 32) {
            float4 v = *(const float4*)(wr + k);
            s_ws[row * WS_PAD + k + 0] = v.x;
            s_ws[row * WS_PAD + k + 1] = v.y;
            s_ws[row * WS_PAD + k + 2] = v.z;
            s_ws[row * WS_PAD + k + 3] = v.w;
        }
    }
    __syncthreads();

    int row = tid >> 3;      // 0..31 gate row (compute phase)
    int bq  = tid & 7;       // batch quad

    float* cst  = g_cst[layer];
    float* outp = layer ? dout : g_H0;

    for (int t = 0; t < Sq; t++) {
        const float* hin = g_ht[layer][t & 1];

        float acc0 = 0.f, acc1 = 0.f, acc2 = 0.f, acc3 = 0.f;

        for (int k0 = 0; k0 < Hq; k0 += KB) {
            // stage KB rows of transposed h (each row = 32 floats = 128B)
            {
                int kk = tid >> 3;           // 0..31
                int b4 = (tid & 7) * 4;
#pragma unroll
                for (int r = 0; r < KB / 32; r++) {
                    int k = kk + r * 32;
                    float4 v = __ldcg((const float4*)(hin + (size_t)(k0 + k) * Bq + b4));
                    *(float4*)&Hs[k][b4] = v;
                }
            }
            __syncthreads();

#pragma unroll
            for (int kk = 0; kk < KB; kk += 4) {
                float4 w4 = *(const float4*)&s_ws[row * WS_PAD + k0 + kk];
                float4 h0 = *(const float4*)&Hs[kk + 0][bq * 4];
                float4 h1 = *(const float4*)&Hs[kk + 1][bq * 4];
                float4 h2 = *(const float4*)&Hs[kk + 2][bq * 4];
                float4 h3 = *(const float4*)&Hs[kk + 3][bq * 4];
                acc0 += h0.x * w4.x; acc1 += h0.y * w4.x; acc2 += h0.z * w4.x; acc3 += h0.w * w4.x;
                acc0 += h1.x * w4.y; acc1 += h1.y * w4.y; acc2 += h1.z * w4.y; acc3 += h1.w * w4.y;
                acc0 += h2.x * w4.z; acc1 += h2.y * w4.z; acc2 += h2.z * w4.z; acc3 += h2.w * w4.z;
                acc0 += h3.x * w4.w; acc1 += h3.y * w4.w; acc2 += h3.z * w4.w; acc3 += h3.w * w4.w;
            }
            __syncthreads();
        }

        // recombine into Gs[gate-row][batch]
        Gs[row][bq * 4 + 0] = acc0;
        Gs[row][bq * 4 + 1] = acc1;
        Gs[row][bq * 4 + 2] = acc2;
        Gs[row][bq * 4 + 3] = acc3;
        __syncthreads();

        // epilogue: 256 threads = 8 units x 32 batches
        {
            int uu = tid >> 5;               // 0..7
            int b  = tid & 31;               // 0..31
            size_t gxb = ((size_t)(b * Sq + t)) * NG + u0 + uu;
            float f  = Gs[uu][b]      + __ldcg(&g_Gx[gxb]);
            float ii = Gs[8  + uu][b] + __ldcg(&g_Gx[gxb + 1024]);
            float gg = Gs[16 + uu][b] + __ldcg(&g_Gx[gxb + 2048]);
            float oo = Gs[24 + uu][b] + __ldcg(&g_Gx[gxb + 3072]);

            float sf = 1.f / (1.f + __expf(-f));
            float si = 1.f / (1.f + __expf(-ii));
            float so = 1.f / (1.f + __expf(-oo));

            int su = (u0 + uu) * Bq + b;
            float cn = sf * cst[su] + si * tanhf(gg);
            float hn = so * tanhf(cn);

            cst[su] = cn;
            g_ht[layer][(t + 1) & 1][su] = hn;
            outp[((size_t)(b * Sq + t)) * Hq + u0 + uu] = hn;
        }

        // ---- grid barrier (monotonic counter; reset each launch) ----
        __threadfence();
        __syncthreads();
        if (tid == 0) {
            atomicAdd(&g_bar[layer], 1u);
            unsigned target = (unsigned)NB * (unsigned)(t + 1);
            while (*(volatile unsigned*)&g_bar[layer] < target) { }
        }
        __syncthreads();
    }
}

// ---------------------------------------------------------------------------
// Tail: h_n [L,B,H] then c_n [L,B,H] after outputs. Final parity = 0.
// ---------------------------------------------------------------------------
__global__ void k_final(float* __restrict__ out) {
    int i = blockIdx.x * blockDim.x + threadIdx.x;
    int n = 2 * Bq * Hq;                 // L*B*H
    if (i < n) {
        int l = i / (Bq * Hq);
        int r = i - l * (Bq * Hq);
        int b = r / Hq;
        int u = r - b * Hq;
        out[(size_t)Mq * Hq + i]     = g_ht[l][0][u * Bq + b];
        out[(size_t)Mq * Hq + n + i] = g_cst[l][u * Bq + b];
    }
}

// ---------------------------------------------------------------------------
extern "C" void kernel_launch(void* const* d_in, const int* in_sizes, int n_in,
                              void* d_out, int out_size) {
    const float* x   = (const float*)d_in[0];
    const float* Wx0 = (const float*)d_in[1];
    const float* Wh0 = (const float*)d_in[2];
    const float* bx0 = (const float*)d_in[3];
    const float* bh0 = (const float*)d_in[4];
    const float* Wx1 = (const float*)d_in[5];
    const float* Wh1 = (const float*)d_in[6];
    const float* bx1 = (const float*)d_in[7];
    const float* bh1 = (const float*)d_in[8];
    float* out = (float*)d_out;

    const int ws_bytes = 32 * WS_PAD * 4;   // 131584
    cudaFuncSetAttribute(k_recur, cudaFuncAttributeMaxDynamicSharedMemorySize, ws_bytes);

    k_zero_state<<<(Hq * Bq + 255) / 256, 256>>>();

    dim3 ggrid(NG / 128, Mq / 128);   // (32, 128)

    // Layer 0
    k_gemm_bias<<<ggrid, 256>>>(x, Wx0, bx0, bh0);
    k_recur<<<NB, NT, ws_bytes>>>(Wh0, out, 0);

    // Layer 1
    k_gemm_bias<<<ggrid, 256>>>(nullptr, Wx1, bx1, bh1);
    k_recur<<<NB, NT, ws_bytes>>>(Wh1, out, 1);

    // Tail: h_n, c_n
    if (out_size >= Mq * Hq + 4 * Bq * Hq)
        k_final<<<(2 * Bq * Hq + 255) / 256, 256>>>(out);
}

// round 5
// speedup vs baseline: 1.1868x; 1.1868x over previous
#include <cuda_runtime.h>
#include <cuda_bf16.h>
#include <math.h>
#include <stdint.h>

// Problem constants
#define Bq 32
#define Sq 512
#define Dq 1024
#define Hq 1024
#define NG 4096            // 4*H
#define Mq (Bq * Sq)       // 16384

#define NB 128             // persistent CTAs for recurrence
#define RNT 512            // threads per CTA in recurrent kernel

// ---------------------------------------------------------------------------
// Scratch (device globals -- no allocations allowed)
// ---------------------------------------------------------------------------
static __device__ float g_Gx[(size_t)Mq * NG];             // input-side gates
static __device__ float g_H0[(size_t)Mq * Hq];             // layer-0 outputs [b*S+t][H]
static __device__ float g_ht[2][2][Hq * Bq];               // [layer][parity][unit*32+batch]
static __device__ float g_cst[2][Hq * Bq];                 // [layer][unit*32+batch]
static __device__ unsigned g_bar[2];                       // grid barrier counters
static __device__ __nv_bfloat16 g_Ahi[(size_t)Mq * 1024];  // A operand hi (x or H0)
static __device__ __nv_bfloat16 g_Alo[(size_t)Mq * 1024];  // A operand lo
static __device__ __nv_bfloat16 g_Whi[(size_t)NG * 1024];  // W operand hi
static __device__ __nv_bfloat16 g_Wlo[(size_t)NG * 1024];  // W operand lo

// ---------------------------------------------------------------------------
// Base-ISA tensor helpers (sm_80+ features, valid on sm_103 base target)
// ---------------------------------------------------------------------------
__device__ __forceinline__ uint32_t smem_to_u32(const void* p) {
    uint32_t a;
    asm("{ .reg .u64 t; cvta.to.shared.u64 t, %1; cvt.u32.u64 %0, t; }" : "=r"(a) : "l"(p));
    return a;
}

#define LDSM_X4(r, addr) \
    asm volatile("ldmatrix.sync.aligned.m8n8.x4.shared.b16 {%0,%1,%2,%3}, [%4];" \
        : "=r"((r)[0]), "=r"((r)[1]), "=r"((r)[2]), "=r"((r)[3]) : "r"(addr))

#define MMA16816(d, a, b0, b1) \
    asm volatile("mma.sync.aligned.m16n8k16.row.col.f32.bf16.bf16.f32 " \
        "{%0,%1,%2,%3}, {%4,%5,%6,%7}, {%8,%9}, {%0,%1,%2,%3};" \
        : "+f"((d)[0]), "+f"((d)[1]), "+f"((d)[2]), "+f"((d)[3]) \
        : "r"((a)[0]), "r"((a)[1]), "r"((a)[2]), "r"((a)[3]), "r"(b0), "r"(b1))

#define CP_ASYNC16(saddr, gptr) \
    asm volatile("cp.async.cg.shared.global [%0], [%1], 16;" :: "r"(saddr), "l"(gptr))
#define CP_COMMIT() asm volatile("cp.async.commit_group;" ::: "memory")
#define CP_WAIT(n)  asm volatile("cp.async.wait_group %0;" :: "n"(n) : "memory")

// ---------------------------------------------------------------------------
// Zero recurrent state + barrier counters
// ---------------------------------------------------------------------------
__global__ void k_zero_state() {
    int i = blockIdx.x * blockDim.x + threadIdx.x;
    if (i < Hq * Bq) {
        g_ht[0][0][i] = 0.f; g_ht[0][1][i] = 0.f;
        g_ht[1][0][i] = 0.f; g_ht[1][1][i] = 0.f;
        g_cst[0][i] = 0.f;   g_cst[1][i] = 0.f;
    }
    if (i == 0) { g_bar[0] = 0u; g_bar[1] = 0u; }
}

// ---------------------------------------------------------------------------
// fp32 -> bf16 (hi, lo) split: hi = rn(f), lo = rn(f - hi)
// ---------------------------------------------------------------------------
__global__ void k_split(const float* __restrict__ src,
                        __nv_bfloat16* __restrict__ hi,
                        __nv_bfloat16* __restrict__ lo, int n4)
{
    int i = blockIdx.x * blockDim.x + threadIdx.x;
    if (i >= n4) return;
    float4 v = ((const float4*)src)[i];
    __nv_bfloat16 h0 = __float2bfloat16(v.x), h1 = __float2bfloat16(v.y);
    __nv_bfloat16 h2 = __float2bfloat16(v.z), h3 = __float2bfloat16(v.w);
    __nv_bfloat16 l0 = __float2bfloat16(v.x - __bfloat162float(h0));
    __nv_bfloat16 l1 = __float2bfloat16(v.y - __bfloat162float(h1));
    __nv_bfloat16 l2 = __float2bfloat16(v.z - __bfloat162float(h2));
    __nv_bfloat16 l3 = __float2bfloat16(v.w - __bfloat162float(h3));
    ((__nv_bfloat162*)hi)[i * 2 + 0] = __nv_bfloat162(h0, h1);
    ((__nv_bfloat162*)hi)[i * 2 + 1] = __nv_bfloat162(h2, h3);
    ((__nv_bfloat162*)lo)[i * 2 + 0] = __nv_bfloat162(l0, l1);
    ((__nv_bfloat162*)lo)[i * 2 + 1] = __nv_bfloat162(l2, l3);
}

// ---------------------------------------------------------------------------
// Tensor-core GEMM via mma.sync (base ISA):
//   g_Gx[M,4096] = (Ahi+Alo)[M,1024] @ (Whi+Wlo)[4096,1024]^T  (3-term)
// CTA tile 128x128, BK=32, 8 warps of 64(m)x32(n), cp.async double buffer.
// Smem per buffer: 4 tiles (Ah, Al, Wh, Wl) of [128][40] bf16 (pad 8 halves).
// ---------------------------------------------------------------------------
#define TILE_H   (128 * 40)                 // halves per tile
#define GBUF_BYTES (4 * TILE_H * 2)         // 40960
#define GSMEM_BYTES (2 * GBUF_BYTES)        // 81920

__global__ __launch_bounds__(256, 1) void k_gemm_mma()
{
    extern __shared__ __align__(16) char smem[];
    uint32_t sm_base = smem_to_u32(smem);
    int tid = threadIdx.x;
    int bn = blockIdx.x * 128;     // W-row (gate) tile
    int bm = blockIdx.y * 128;     // A-row tile
    int lane = tid & 31;
    int wid = tid >> 5;
    int wm = (wid & 1) * 64;       // warp m offset
    int wn = (wid >> 1) * 32;      // warp n offset

    const __nv_bfloat16* gsrc[4];
    gsrc[0] = g_Ahi + (size_t)bm * 1024;
    gsrc[1] = g_Alo + (size_t)bm * 1024;
    gsrc[2] = g_Whi + (size_t)bn * 1024;
    gsrc[3] = g_Wlo + (size_t)bn * 1024;

    float acc[4][4][4];
#pragma unroll
    for (int i = 0; i < 4; i++)
#pragma unroll
        for (int j = 0; j < 4; j++)
#pragma unroll
            for (int k = 0; k < 4; k++) acc[i][j][k] = 0.f;

    // ldmatrix per-lane addressing (within a tile, in halves)
    int row_a = lane & 15;
    int kh_a  = lane >> 4;               // 0/1 -> k halves 0-7 / 8-15
    int row_b = (lane & 7) + ((lane >> 4) << 3);
    int kh_b  = (lane >> 3) & 1;

#define ISSUE_CHUNK(ch) do {                                                   \
    int _k0 = (ch) * 32;                                                       \
    uint32_t _sb = sm_base + ((ch) & 1) * GBUF_BYTES;                          \
    _Pragma("unroll")                                                          \
    for (int _t = 0; _t < 4; _t++) {                                           \
        const __nv_bfloat16* _g = gsrc[_t] + _k0;                              \
        uint32_t _sbt = _sb + _t * (TILE_H * 2);                               \
        _Pragma("unroll")                                                      \
        for (int _r = 0; _r < 2; _r++) {                                       \
            int _v = tid + _r * 256;                                           \
            int _row = _v >> 2, _k8 = (_v & 3) * 8;                            \
            CP_ASYNC16(_sbt + (uint32_t)(_row * 40 + _k8) * 2,                 \
                       _g + (size_t)_row * 1024 + _k8);                        \
        }                                                                      \
    }                                                                          \
    CP_COMMIT();                                                               \
} while (0)

    ISSUE_CHUNK(0);

    for (int ch = 0; ch < 32; ch++) {
        if (ch + 1 < 32) { ISSUE_CHUNK(ch + 1); CP_WAIT(1); }
        else             { CP_WAIT(0); }
        __syncthreads();

        uint32_t sb = sm_base + (ch & 1) * GBUF_BYTES;
        uint32_t ah_t = sb;
        uint32_t al_t = sb + TILE_H * 2;
        uint32_t wh_t = sb + 2 * TILE_H * 2;
        uint32_t wl_t = sb + 3 * TILE_H * 2;

#pragma unroll
        for (int kk = 0; kk < 2; kk++) {
            uint32_t ah[4][4], al[4][4], wh[2][4], wl[2][4];
#pragma unroll
            for (int mi = 0; mi < 4; mi++) {
                uint32_t off = (uint32_t)((wm + mi * 16 + row_a) * 40 + kk * 16 + kh_a * 8) * 2;
                LDSM_X4(ah[mi], ah_t + off);
                LDSM_X4(al[mi], al_t + off);
            }
#pragma unroll
            for (int p = 0; p < 2; p++) {
                uint32_t off = (uint32_t)((wn + p * 16 + row_b) * 40 + kk * 16 + kh_b * 8) * 2;
                LDSM_X4(wh[p], wh_t + off);
                LDSM_X4(wl[p], wl_t + off);
            }
#pragma unroll
            for (int mi = 0; mi < 4; mi++)
#pragma unroll
                for (int ni = 0; ni < 4; ni++) {
                    int pr = ni >> 1, sb2 = (ni & 1) * 2;
                    MMA16816(acc[mi][ni], ah[mi], wh[pr][sb2], wh[pr][sb2 + 1]);
                    MMA16816(acc[mi][ni], ah[mi], wl[pr][sb2], wl[pr][sb2 + 1]);
                    MMA16816(acc[mi][ni], al[mi], wh[pr][sb2], wh[pr][sb2 + 1]);
                }
        }
        __syncthreads();
    }
#undef ISSUE_CHUNK

    // epilogue: fp32 accumulators -> g_Gx (float2 stores)
    int g = lane >> 2, tig = lane & 3;
#pragma unroll
    for (int mi = 0; mi < 4; mi++) {
#pragma unroll
        for (int ni = 0; ni < 4; ni++) {
            int row = bm + wm + mi * 16 + g;
            int col = bn + wn + ni * 8 + tig * 2;
            float2 v0 = make_float2(acc[mi][ni][0], acc[mi][ni][1]);
            float2 v1 = make_float2(acc[mi][ni][2], acc[mi][ni][3]);
            *(float2*)&g_Gx[(size_t)row * NG + col] = v0;
            *(float2*)&g_Gx[(size_t)(row + 8) * NG + col] = v1;
        }
    }
}

// ---------------------------------------------------------------------------
// Persistent recurrent kernel, 512 threads: in-CTA k-split (2 halves of 512).
// Block bx owns units u0 = bx*8..+7 (32 gate rows), all 32 batches.
// Wh slice (32x1024 fp32) cached in dynamic smem for all 512 steps.
// Bias (bx+bh) folded here.
// ---------------------------------------------------------------------------
#define RSM_BYTES (32 * 1028 * 4)   // 131584

__global__ __launch_bounds__(RNT) void k_recur(
    const float* __restrict__ Wh, const float* __restrict__ b1,
    const float* __restrict__ b2, float* __restrict__ dout, int layer)
{
    extern __shared__ __align__(16) char smem[];
    float* ws = (float*)smem;               // [32][1028]
    __shared__ float Hs[2][64][32];         // [khalf][k][batch]
    __shared__ float Gs[2][32][33];         // [khalf][gate-row][batch]
    __shared__ float bias_s[32];

    int tid = threadIdx.x;
    int u0 = blockIdx.x * 8;

    // load Wh slice: row r covers gate (r>>3), unit u0+(r&7)
    {
        int rw = tid >> 4;                  // 0..31
        int k4 = (tid & 15) * 4;            // 0..60
        int jrow = (rw >> 3) * Hq + u0 + (rw & 7);
        const float* wr = Wh + (size_t)jrow * Hq;
        for (int k = k4; k < Hq; k += 64)
            *(float4*)&ws[rw * 1028 + k] = *(const float4*)(wr + k);
    }
    if (tid < 32) {
        int jrow = (tid >> 3) * Hq + u0 + (tid & 7);
        bias_s[tid] = b1[jrow] + b2[jrow];
    }
    __syncthreads();

    int kh  = tid >> 8;      // k half
    int tl  = tid & 255;
    int row = tl >> 3;       // gate row 0..31
    int bq  = tl & 7;        // batch quad

    float* cst  = g_cst[layer];
    float* outp = layer ? dout : g_H0;

    for (int t = 0; t < Sq; t++) {
        const float* hin = g_ht[layer][t & 1];
        float a0 = 0.f, a1 = 0.f, a2 = 0.f, a3 = 0.f;

        for (int j = 0; j < 8; j++) {
            int k0 = (kh << 9) + (j << 6);
            {
                int kk = tl >> 3;            // 0..31
                int b4 = (tl & 7) * 4;
                float4 v0 = __ldcg((const float4*)(hin + (size_t)(k0 + kk) * Bq + b4));
                float4 v1 = __ldcg((const float4*)(hin + (size_t)(k0 + kk + 32) * Bq + b4));
                *(float4*)&Hs[kh][kk][b4] = v0;
                *(float4*)&Hs[kh][kk + 32][b4] = v1;
            }
            __syncthreads();

            const float* wrow = &ws[row * 1028 + k0];
#pragma unroll
            for (int kk = 0; kk < 64; kk += 4) {
                float4 w4 = *(const float4*)(wrow + kk);
                float4 h0 = *(const float4*)&Hs[kh][kk + 0][bq * 4];
                float4 h1 = *(const float4*)&Hs[kh][kk + 1][bq * 4];
                float4 h2 = *(const float4*)&Hs[kh][kk + 2][bq * 4];
                float4 h3 = *(const float4*)&Hs[kh][kk + 3][bq * 4];
                a0 += h0.x * w4.x; a1 += h0.y * w4.x; a2 += h0.z * w4.x; a3 += h0.w * w4.x;
                a0 += h1.x * w4.y; a1 += h1.y * w4.y; a2 += h1.z * w4.y; a3 += h1.w * w4.y;
                a0 += h2.x * w4.z; a1 += h2.y * w4.z; a2 += h2.z * w4.z; a3 += h2.w * w4.z;
                a0 += h3.x * w4.w; a1 += h3.y * w4.w; a2 += h3.z * w4.w; a3 += h3.w * w4.w;
            }
            __syncthreads();
        }

        Gs[kh][row][bq * 4 + 0] = a0;
        Gs[kh][row][bq * 4 + 1] = a1;
        Gs[kh][row][bq * 4 + 2] = a2;
        Gs[kh][row][bq * 4 + 3] = a3;
        __syncthreads();

        if (tid < 256) {
            int uu = tid >> 5;               // 0..7
            int b  = tid & 31;               // 0..31
            size_t gxb = ((size_t)(b * Sq + t)) * NG + u0 + uu;
            float f  = Gs[0][uu][b]      + Gs[1][uu][b]      + bias_s[uu]      + __ldcg(&g_Gx[gxb]);
            float ii = Gs[0][8 + uu][b]  + Gs[1][8 + uu][b]  + bias_s[8 + uu]  + __ldcg(&g_Gx[gxb + 1024]);
            float gg = Gs[0][16 + uu][b] + Gs[1][16 + uu][b] + bias_s[16 + uu] + __ldcg(&g_Gx[gxb + 2048]);
            float oo = Gs[0][24 + uu][b] + Gs[1][24 + uu][b] + bias_s[24 + uu] + __ldcg(&g_Gx[gxb + 3072]);

            float sf = 1.f / (1.f + __expf(-f));
            float si = 1.f / (1.f + __expf(-ii));
            float so = 1.f / (1.f + __expf(-oo));

            int su = (u0 + uu) * Bq + b;
            float cn = sf * cst[su] + si * tanhf(gg);
            float hn = so * tanhf(cn);

            cst[su] = cn;
            g_ht[layer][(t + 1) & 1][su] = hn;
            outp[((size_t)(b * Sq + t)) * Hq + u0 + uu] = hn;
        }

        // grid barrier
        __threadfence();
        __syncthreads();
        if (tid == 0) {
            atomicAdd(&g_bar[layer], 1u);
            unsigned target = (unsigned)NB * (unsigned)(t + 1);
            while (*(volatile unsigned*)&g_bar[layer] < target) { }
        }
        __syncthreads();
    }
}

// ---------------------------------------------------------------------------
// Tail: h_n [L,B,H] then c_n [L,B,H]. Final parity = 0.
// ---------------------------------------------------------------------------
__global__ void k_final(float* __restrict__ out) {
    int i = blockIdx.x * blockDim.x + threadIdx.x;
    int n = 2 * Bq * Hq;
    if (i < n) {
        int l = i / (Bq * Hq);
        int r = i - l * (Bq * Hq);
        int b = r / Hq;
        int u = r - b * Hq;
        out[(size_t)Mq * Hq + i]     = g_ht[l][0][u * Bq + b];
        out[(size_t)Mq * Hq + n + i] = g_cst[l][u * Bq + b];
    }
}

// ---------------------------------------------------------------------------
extern "C" void kernel_launch(void* const* d_in, const int* in_sizes, int n_in,
                              void* d_out, int out_size) {
    const float* x   = (const float*)d_in[0];
    const float* Wx0 = (const float*)d_in[1];
    const float* Wh0 = (const float*)d_in[2];
    const float* bx0 = (const float*)d_in[3];
    const float* bh0 = (const float*)d_in[4];
    const float* Wx1 = (const float*)d_in[5];
    const float* Wh1 = (const float*)d_in[6];
    const float* bx1 = (const float*)d_in[7];
    const float* bh1 = (const float*)d_in[8];
    float* out = (float*)d_out;

    cudaFuncSetAttribute(k_gemm_mma, cudaFuncAttributeMaxDynamicSharedMemorySize, GSMEM_BYTES);
    cudaFuncSetAttribute(k_recur,    cudaFuncAttributeMaxDynamicSharedMemorySize, RSM_BYTES);

    static __nv_bfloat16 *pAhi = nullptr, *pAlo = nullptr, *pWhi = nullptr, *pWlo = nullptr;
    static float* pH0 = nullptr;
    if (!pAhi) {
        cudaGetSymbolAddress((void**)&pAhi, g_Ahi);
        cudaGetSymbolAddress((void**)&pAlo, g_Alo);
        cudaGetSymbolAddress((void**)&pWhi, g_Whi);
        cudaGetSymbolAddress((void**)&pWlo, g_Wlo);
        cudaGetSymbolAddress((void**)&pH0,  g_H0);
    }

    k_zero_state<<<(Hq * Bq + 255) / 256, 256>>>();

    const int nA4 = Mq * 1024 / 4;
    const int nW4 = NG * 1024 / 4;
    dim3 ggrid(NG / 128, Mq / 128);      // (32, 128)

    // Layer 0
    k_split<<<(nA4 + 255) / 256, 256>>>(x, pAhi, pAlo, nA4);
    k_split<<<(nW4 + 255) / 256, 256>>>(Wx0, pWhi, pWlo, nW4);
    k_gemm_mma<<<ggrid, 256, GSMEM_BYTES>>>();
    k_recur<<<NB, RNT, RSM_BYTES>>>(Wh0, bx0, bh0, out, 0);

    // Layer 1
    k_split<<<(nA4 + 255) / 256, 256>>>(pH0, pAhi, pAlo, nA4);
    k_split<<<(nW4 + 255) / 256, 256>>>(Wx1, pWhi, pWlo, nW4);
    k_gemm_mma<<<ggrid, 256, GSMEM_BYTES>>>();
    k_recur<<<NB, RNT, RSM_BYTES>>>(Wh1, bx1, bh1, out, 1);

    // Tail
    if (out_size >= Mq * Hq + 4 * Bq * Hq)
        k_final<<<(2 * Bq * Hq + 255) / 256, 256>>>(out);
}

// round 6
// speedup vs baseline: 2.9009x; 2.4443x over previous
#include <cuda_runtime.h>
#include <cuda_bf16.h>
#include <math.h>
#include <stdint.h>

// Problem constants
#define Bq 32
#define Sq 512
#define Dq 1024
#define Hq 1024
#define NG 4096            // 4*H
#define Mq (Bq * Sq)       // 16384

#define NB 128             // persistent CTAs for recurrence
#define RNT 512            // threads per CTA in recurrent kernel

// ---------------------------------------------------------------------------
// Scratch (device globals -- no allocations allowed)
// ---------------------------------------------------------------------------
static __device__ float g_Gx[(size_t)Mq * NG];             // input-side gates
static __device__ float g_H0[(size_t)Mq * Hq];             // layer-0 outputs [b*S+t][H]
static __device__ float g_htf[2][Hq * Bq];                 // final h (t=511) [u*32+b]
static __device__ float g_cst[2][Hq * Bq];                 // final c (t=511) [u*32+b]
static __device__ unsigned g_bar[2];                       // grid barrier counters
static __device__ __nv_bfloat16 g_Ahi[(size_t)Mq * 1024];  // GEMM A hi (x or H0)
static __device__ __nv_bfloat16 g_Alo[(size_t)Mq * 1024];  // GEMM A lo
static __device__ __nv_bfloat16 g_Whi[(size_t)NG * 1024];  // W hi (Wx for GEMM, Wh for recur)
static __device__ __nv_bfloat16 g_Wlo[(size_t)NG * 1024];  // W lo
static __device__ __nv_bfloat16 g_hbh[2][2][Bq * 1024];    // recur h hi [layer][parity][b][k]
static __device__ __nv_bfloat16 g_hbl[2][2][Bq * 1024];    // recur h lo

// ---------------------------------------------------------------------------
// Base-ISA tensor helpers (sm_80+ features, valid on sm_103 base target)
// ---------------------------------------------------------------------------
__device__ __forceinline__ uint32_t smem_to_u32(const void* p) {
    uint32_t a;
    asm("{ .reg .u64 t; cvta.to.shared.u64 t, %1; cvt.u32.u64 %0, t; }" : "=r"(a) : "l"(p));
    return a;
}

#define LDSM_X4(r, addr) \
    asm volatile("ldmatrix.sync.aligned.m8n8.x4.shared.b16 {%0,%1,%2,%3}, [%4];" \
        : "=r"((r)[0]), "=r"((r)[1]), "=r"((r)[2]), "=r"((r)[3]) : "r"(addr))

#define MMA16816(d, a, b0, b1) \
    asm volatile("mma.sync.aligned.m16n8k16.row.col.f32.bf16.bf16.f32 " \
        "{%0,%1,%2,%3}, {%4,%5,%6,%7}, {%8,%9}, {%0,%1,%2,%3};" \
        : "+f"((d)[0]), "+f"((d)[1]), "+f"((d)[2]), "+f"((d)[3]) \
        : "r"((a)[0]), "r"((a)[1]), "r"((a)[2]), "r"((a)[3]), "r"(b0), "r"(b1))

#define CP_ASYNC16(saddr, gptr) \
    asm volatile("cp.async.cg.shared.global [%0], [%1], 16;" :: "r"(saddr), "l"(gptr))
#define CP_COMMIT() asm volatile("cp.async.commit_group;" ::: "memory")
#define CP_WAIT(n)  asm volatile("cp.async.wait_group %0;" :: "n"(n) : "memory")

// ---------------------------------------------------------------------------
// Zero bf16 h state (both layers/parities) + barrier counters
// ---------------------------------------------------------------------------
__global__ void k_zero_state() {
    int i = blockIdx.x * blockDim.x + threadIdx.x;
    int n = 2 * 2 * Bq * 1024 / 2;           // u32 count
    if (i < n) {
        ((uint32_t*)g_hbh)[i] = 0u;
        ((uint32_t*)g_hbl)[i] = 0u;
    }
    if (i == 0) { g_bar[0] = 0u; g_bar[1] = 0u; }
}

// ---------------------------------------------------------------------------
// fp32 -> bf16 (hi, lo) split: hi = rn(f), lo = rn(f - hi)
// ---------------------------------------------------------------------------
__global__ void k_split(const float* __restrict__ src,
                        __nv_bfloat16* __restrict__ hi,
                        __nv_bfloat16* __restrict__ lo, int n4)
{
    int i = blockIdx.x * blockDim.x + threadIdx.x;
    if (i >= n4) return;
    float4 v = ((const float4*)src)[i];
    __nv_bfloat16 h0 = __float2bfloat16(v.x), h1 = __float2bfloat16(v.y);
    __nv_bfloat16 h2 = __float2bfloat16(v.z), h3 = __float2bfloat16(v.w);
    __nv_bfloat16 l0 = __float2bfloat16(v.x - __bfloat162float(h0));
    __nv_bfloat16 l1 = __float2bfloat16(v.y - __bfloat162float(h1));
    __nv_bfloat16 l2 = __float2bfloat16(v.z - __bfloat162float(h2));
    __nv_bfloat16 l3 = __float2bfloat16(v.w - __bfloat162float(h3));
    ((__nv_bfloat162*)hi)[i * 2 + 0] = __nv_bfloat162(h0, h1);
    ((__nv_bfloat162*)hi)[i * 2 + 1] = __nv_bfloat162(h2, h3);
    ((__nv_bfloat162*)lo)[i * 2 + 0] = __nv_bfloat162(l0, l1);
    ((__nv_bfloat162*)lo)[i * 2 + 1] = __nv_bfloat162(l2, l3);
}

// ---------------------------------------------------------------------------
// Tensor-core GEMM via mma.sync (unchanged, verified):
//   g_Gx[M,4096] = (Ahi+Alo)[M,1024] @ (Whi+Wlo)[4096,1024]^T  (3-term)
// ---------------------------------------------------------------------------
#define TILE_H   (128 * 40)
#define GBUF_BYTES (4 * TILE_H * 2)
#define GSMEM_BYTES (2 * GBUF_BYTES)

__global__ __launch_bounds__(256, 1) void k_gemm_mma()
{
    extern __shared__ __align__(16) char smem[];
    uint32_t sm_base = smem_to_u32(smem);
    int tid = threadIdx.x;
    int bn = blockIdx.x * 128;
    int bm = blockIdx.y * 128;
    int lane = tid & 31;
    int wid = tid >> 5;
    int wm = (wid & 1) * 64;
    int wn = (wid >> 1) * 32;

    const __nv_bfloat16* gsrc[4];
    gsrc[0] = g_Ahi + (size_t)bm * 1024;
    gsrc[1] = g_Alo + (size_t)bm * 1024;
    gsrc[2] = g_Whi + (size_t)bn * 1024;
    gsrc[3] = g_Wlo + (size_t)bn * 1024;

    float acc[4][4][4];
#pragma unroll
    for (int i = 0; i < 4; i++)
#pragma unroll
        for (int j = 0; j < 4; j++)
#pragma unroll
            for (int k = 0; k < 4; k++) acc[i][j][k] = 0.f;

    int row_a = lane & 15;
    int kh_a  = lane >> 4;
    int row_b = (lane & 7) + ((lane >> 4) << 3);
    int kh_b  = (lane >> 3) & 1;

#define ISSUE_CHUNK(ch) do {                                                   \
    int _k0 = (ch) * 32;                                                       \
    uint32_t _sb = sm_base + ((ch) & 1) * GBUF_BYTES;                          \
    _Pragma("unroll")                                                          \
    for (int _t = 0; _t < 4; _t++) {                                           \
        const __nv_bfloat16* _g = gsrc[_t] + _k0;                              \
        uint32_t _sbt = _sb + _t * (TILE_H * 2);                               \
        _Pragma("unroll")                                                      \
        for (int _r = 0; _r < 2; _r++) {                                       \
            int _v = tid + _r * 256;                                           \
            int _row = _v >> 2, _k8 = (_v & 3) * 8;                            \
            CP_ASYNC16(_sbt + (uint32_t)(_row * 40 + _k8) * 2,                 \
                       _g + (size_t)_row * 1024 + _k8);                        \
        }                                                                      \
    }                                                                          \
    CP_COMMIT();                                                               \
} while (0)

    ISSUE_CHUNK(0);

    for (int ch = 0; ch < 32; ch++) {
        if (ch + 1 < 32) { ISSUE_CHUNK(ch + 1); CP_WAIT(1); }
        else             { CP_WAIT(0); }
        __syncthreads();

        uint32_t sb = sm_base + (ch & 1) * GBUF_BYTES;
        uint32_t ah_t = sb;
        uint32_t al_t = sb + TILE_H * 2;
        uint32_t wh_t = sb + 2 * TILE_H * 2;
        uint32_t wl_t = sb + 3 * TILE_H * 2;

#pragma unroll
        for (int kk = 0; kk < 2; kk++) {
            uint32_t ah[4][4], al[4][4], wh[2][4], wl[2][4];
#pragma unroll
            for (int mi = 0; mi < 4; mi++) {
                uint32_t off = (uint32_t)((wm + mi * 16 + row_a) * 40 + kk * 16 + kh_a * 8) * 2;
                LDSM_X4(ah[mi], ah_t + off);
                LDSM_X4(al[mi], al_t + off);
            }
#pragma unroll
            for (int p = 0; p < 2; p++) {
                uint32_t off = (uint32_t)((wn + p * 16 + row_b) * 40 + kk * 16 + kh_b * 8) * 2;
                LDSM_X4(wh[p], wh_t + off);
                LDSM_X4(wl[p], wl_t + off);
            }
#pragma unroll
            for (int mi = 0; mi < 4; mi++)
#pragma unroll
                for (int ni = 0; ni < 4; ni++) {
                    int pr = ni >> 1, sb2 = (ni & 1) * 2;
                    MMA16816(acc[mi][ni], ah[mi], wh[pr][sb2], wh[pr][sb2 + 1]);
                    MMA16816(acc[mi][ni], ah[mi], wl[pr][sb2], wl[pr][sb2 + 1]);
                    MMA16816(acc[mi][ni], al[mi], wh[pr][sb2], wh[pr][sb2 + 1]);
                }
        }
        __syncthreads();
    }
#undef ISSUE_CHUNK

    int g = lane >> 2, tig = lane & 3;
#pragma unroll
    for (int mi = 0; mi < 4; mi++) {
#pragma unroll
        for (int ni = 0; ni < 4; ni++) {
            int row = bm + wm + mi * 16 + g;
            int col = bn + wn + ni * 8 + tig * 2;
            float2 v0 = make_float2(acc[mi][ni][0], acc[mi][ni][1]);
            float2 v1 = make_float2(acc[mi][ni][2], acc[mi][ni][3]);
            *(float2*)&g_Gx[(size_t)row * NG + col] = v0;
            *(float2*)&g_Gx[(size_t)(row + 8) * NG + col] = v1;
        }
    }
}

// ---------------------------------------------------------------------------
// Tensor-core persistent recurrence.
// 128 CTAs x 512 thr. CTA bx owns units u0=bx*8..+7 => 32 local gate rows
// (r = gate*8+uu, gates f,i,g,o). 16 warps: wid = mi + 2*ks,
//   mi in {0,1}: m-half (rows mi*16..+15), ks in {0..7}: k-slice 128 wide.
// Wh slice (hi+lo) held in A-fragments in REGISTERS for the whole layer.
// Per step: h (bf16 hi/lo, [batch][k]) -> smem -> ldmatrix B-frags -> 96 MMA
// -> k-split partials in smem -> fused LSTM epilogue (c in registers).
// ---------------------------------------------------------------------------
#define HPAD 1032                              // halves per smem row (1024+8)
#define SH_BYTES (Bq * HPAD * 2)               // one h tile (hi or lo): 66048
#define SP_OFF   (2 * SH_BYTES)                // partials offset: 132096
#define SP_BYTES (16 * 16 * 34 * 4)            // [2*8][16][34] f32: 34816
#define SBIAS_OFF (SP_OFF + SP_BYTES)          // 166912
#define RSMEM_BYTES (SBIAS_OFF + 128)          // 167040

__global__ __launch_bounds__(RNT, 1) void k_recur_mma(
    const float* __restrict__ b1, const float* __restrict__ b2,
    float* __restrict__ dout, int layer)
{
    extern __shared__ __align__(16) char smem[];
    __nv_bfloat16* sHhi = (__nv_bfloat16*)smem;
    __nv_bfloat16* sHlo = (__nv_bfloat16*)(smem + SH_BYTES);
    float* sP    = (float*)(smem + SP_OFF);
    float* sBias = (float*)(smem + SBIAS_OFF);

    int tid  = threadIdx.x;
    int lane = tid & 31;
    int wid  = tid >> 5;
    int mi   = wid & 1;
    int ks   = wid >> 1;
    int u0   = blockIdx.x * 8;

    uint32_t sHhi_u = smem_to_u32(sHhi);
    uint32_t sHlo_u = smem_to_u32(sHlo);

    // ---- prologue: load Wh slice into A-fragments (registers) ----
    uint32_t a_hi[8][4], a_lo[8][4];
    {
        // stage rows r=0..31: global row (r>>3)*1024 + u0 + (r&7)
        int r = tid >> 4, c16 = tid & 15;
        int jrow = (r >> 3) * Hq + u0 + (r & 7);
        int arow = mi * 16 + (lane & 15);
        int acol8 = (lane >> 4) * 8;
        uint32_t abase = sHhi_u + (uint32_t)(arow * HPAD + acol8) * 2;

        const __nv_bfloat16* wsrc = g_Whi + (size_t)jrow * 1024;
#pragma unroll
        for (int j = 0; j < 8; j++) {
            int cc = c16 + j * 16;
            *(uint4*)(sHhi + r * HPAD + cc * 8) = __ldcg((const uint4*)(wsrc + cc * 8));
        }
        __syncthreads();
#pragma unroll
        for (int kg = 0; kg < 8; kg++)
            LDSM_X4(a_hi[kg], abase + (uint32_t)((ks * 128 + kg * 16) * 2));
        __syncthreads();

        wsrc = g_Wlo + (size_t)jrow * 1024;
#pragma unroll
        for (int j = 0; j < 8; j++) {
            int cc = c16 + j * 16;
            *(uint4*)(sHhi + r * HPAD + cc * 8) = __ldcg((const uint4*)(wsrc + cc * 8));
        }
        __syncthreads();
#pragma unroll
        for (int kg = 0; kg < 8; kg++)
            LDSM_X4(a_lo[kg], abase + (uint32_t)((ks * 128 + kg * 16) * 2));
        __syncthreads();
    }

    if (tid < 32) {
        int jrow = (tid >> 3) * Hq + u0 + (tid & 7);
        sBias[tid] = b1[jrow] + b2[jrow];
    }

    // B-fragment ldmatrix lane addressing (batch-row major [b][k], stride HPAD)
    int brow  = ((lane >> 4) * 8) + (lane & 7);      // ng0/ng1 within a pair
    int bcol8 = ((lane >> 3) & 1) * 8;
    uint32_t bh_base0 = sHhi_u + (uint32_t)(brow * HPAD + bcol8) * 2;            // ng 0,1
    uint32_t bh_base2 = bh_base0 + (uint32_t)(16 * HPAD) * 2;                    // ng 2,3
    uint32_t bl_base0 = sHlo_u + (uint32_t)(brow * HPAD + bcol8) * 2;
    uint32_t bl_base2 = bl_base0 + (uint32_t)(16 * HPAD) * 2;
    uint32_t kslice = (uint32_t)(ks * 128) * 2;

    // epilogue ownership: thread (b, uu), c in register
    int eb = tid >> 3, euu = tid & 7;                // valid for tid<256
    float c_reg = 0.f;

    float* outp = layer ? dout : g_H0;
    int hload_b = tid >> 4, hload_c = tid & 15;

    for (int t = 0; t < Sq; t++) {
        // ---- stage h tiles (hi + lo), [32][1024] bf16 each ----
        {
            const __nv_bfloat16* hh = g_hbh[layer][t & 1] + hload_b * 1024;
            const __nv_bfloat16* hl = g_hbl[layer][t & 1] + hload_b * 1024;
            __nv_bfloat16* dh = sHhi + hload_b * HPAD;
            __nv_bfloat16* dl = sHlo + hload_b * HPAD;
#pragma unroll
            for (int j = 0; j < 8; j++) {
                int cc = (hload_c + j * 16) * 8;
                *(uint4*)(dh + cc) = __ldcg((const uint4*)(hh + cc));
                *(uint4*)(dl + cc) = __ldcg((const uint4*)(hl + cc));
            }
        }
        __syncthreads();

        // ---- 96 MMAs per warp ----
        float acc[4][4];
#pragma unroll
        for (int nf = 0; nf < 4; nf++)
#pragma unroll
            for (int e = 0; e < 4; e++) acc[nf][e] = 0.f;

#pragma unroll
        for (int kg = 0; kg < 8; kg++) {
            uint32_t koff = kslice + (uint32_t)(kg * 16) * 2;
            uint32_t bh[8], bl[8];
            LDSM_X4(&bh[0], bh_base0 + koff);
            LDSM_X4(&bh[4], bh_base2 + koff);
            LDSM_X4(&bl[0], bl_base0 + koff);
            LDSM_X4(&bl[4], bl_base2 + koff);
#pragma unroll
            for (int nf = 0; nf < 4; nf++) {
                MMA16816(acc[nf], a_hi[kg], bh[nf * 2], bh[nf * 2 + 1]);
                MMA16816(acc[nf], a_hi[kg], bl[nf * 2], bl[nf * 2 + 1]);
                MMA16816(acc[nf], a_lo[kg], bh[nf * 2], bh[nf * 2 + 1]);
            }
        }

        // ---- write k-split partials: sP[(mi*8+ks)*16 + r16][34] ----
        {
            int r16 = lane >> 2;
            int colb = (lane & 3) * 2;
            float* base = sP + (size_t)((mi * 8 + ks) * 16) * 34;
#pragma unroll
            for (int nf = 0; nf < 4; nf++) {
                *(float2*)&base[(r16)     * 34 + nf * 8 + colb] = make_float2(acc[nf][0], acc[nf][1]);
                *(float2*)&base[(r16 + 8) * 34 + nf * 8 + colb] = make_float2(acc[nf][2], acc[nf][3]);
            }
        }
        __syncthreads();

        // ---- fused LSTM epilogue (tid<256: thread = (batch eb, unit euu)) ----
        if (tid < 256) {
            size_t gxb = ((size_t)(eb * Sq + t)) * NG + u0 + euu;
            float gate[4];
#pragma unroll
            for (int g = 0; g < 4; g++) {
                int r = g * 8 + euu;
                int gmi = r >> 4, r16 = r & 15;
                float s = 0.f;
#pragma unroll
                for (int kss = 0; kss < 8; kss++)
                    s += sP[((gmi * 8 + kss) * 16 + r16) * 34 + eb];
                gate[g] = s + sBias[r] + __ldcg(&g_Gx[gxb + (size_t)g * 1024]);
            }
            float sf = 1.f / (1.f + __expf(-gate[0]));
            float si = 1.f / (1.f + __expf(-gate[1]));
            float so = 1.f / (1.f + __expf(-gate[3]));
            float cn = sf * c_reg + si * tanhf(gate[2]);
            float hn = so * tanhf(cn);
            c_reg = cn;

            __nv_bfloat16 hhi = __float2bfloat16(hn);
            __nv_bfloat16 hlo = __float2bfloat16(hn - __bfloat162float(hhi));
            int hp = (t + 1) & 1;
            g_hbh[layer][hp][eb * 1024 + u0 + euu] = hhi;
            g_hbl[layer][hp][eb * 1024 + u0 + euu] = hlo;
            outp[((size_t)(eb * Sq + t)) * Hq + u0 + euu] = hn;
            if (t == Sq - 1) {
                int su = (u0 + euu) * Bq + eb;
                g_htf[layer][su] = hn;
                g_cst[layer][su] = cn;
            }
        }

        // ---- grid barrier ----
        __threadfence();
        __syncthreads();
        if (tid == 0) {
            atomicAdd(&g_bar[layer], 1u);
            unsigned target = (unsigned)NB * (unsigned)(t + 1);
            while (*(volatile unsigned*)&g_bar[layer] < target) { }
        }
        __syncthreads();
    }
}

// ---------------------------------------------------------------------------
// Tail: h_n [L,B,H] then c_n [L,B,H] after outputs.
// ---------------------------------------------------------------------------
__global__ void k_final(float* __restrict__ out) {
    int i = blockIdx.x * blockDim.x + threadIdx.x;
    int n = 2 * Bq * Hq;
    if (i < n) {
        int l = i / (Bq * Hq);
        int r = i - l * (Bq * Hq);
        int b = r / Hq;
        int u = r - b * Hq;
        out[(size_t)Mq * Hq + i]     = g_htf[l][u * Bq + b];
        out[(size_t)Mq * Hq + n + i] = g_cst[l][u * Bq + b];
    }
}

// ---------------------------------------------------------------------------
extern "C" void kernel_launch(void* const* d_in, const int* in_sizes, int n_in,
                              void* d_out, int out_size) {
    const float* x   = (const float*)d_in[0];
    const float* Wx0 = (const float*)d_in[1];
    const float* Wh0 = (const float*)d_in[2];
    const float* bx0 = (const float*)d_in[3];
    const float* bh0 = (const float*)d_in[4];
    const float* Wx1 = (const float*)d_in[5];
    const float* Wh1 = (const float*)d_in[6];
    const float* bx1 = (const float*)d_in[7];
    const float* bh1 = (const float*)d_in[8];
    float* out = (float*)d_out;

    cudaFuncSetAttribute(k_gemm_mma,  cudaFuncAttributeMaxDynamicSharedMemorySize, GSMEM_BYTES);
    cudaFuncSetAttribute(k_recur_mma, cudaFuncAttributeMaxDynamicSharedMemorySize, RSMEM_BYTES);

    static __nv_bfloat16 *pAhi = nullptr, *pAlo = nullptr, *pWhi = nullptr, *pWlo = nullptr;
    static float* pH0 = nullptr;
    if (!pAhi) {
        cudaGetSymbolAddress((void**)&pAhi, g_Ahi);
        cudaGetSymbolAddress((void**)&pAlo, g_Alo);
        cudaGetSymbolAddress((void**)&pWhi, g_Whi);
        cudaGetSymbolAddress((void**)&pWlo, g_Wlo);
        cudaGetSymbolAddress((void**)&pH0,  g_H0);
    }

    const int nZ = 2 * 2 * Bq * 1024 / 2;
    k_zero_state<<<(nZ + 255) / 256, 256>>>();

    const int nA4 = Mq * 1024 / 4;
    const int nW4 = NG * 1024 / 4;
    dim3 ggrid(NG / 128, Mq / 128);      // (32, 128)

    // Layer 0: Wx0 GEMM, then Wh0 -> bf16 split -> register-resident recurrence
    k_split<<<(nA4 + 255) / 256, 256>>>(x, pAhi, pAlo, nA4);
    k_split<<<(nW4 + 255) / 256, 256>>>(Wx0, pWhi, pWlo, nW4);
    k_gemm_mma<<<ggrid, 256, GSMEM_BYTES>>>();
    k_split<<<(nW4 + 255) / 256, 256>>>(Wh0, pWhi, pWlo, nW4);
    k_recur_mma<<<NB, RNT, RSMEM_BYTES>>>(bx0, bh0, out, 0);

    // Layer 1
    k_split<<<(nA4 + 255) / 256, 256>>>(pH0, pAhi, pAlo, nA4);
    k_split<<<(nW4 + 255) / 256, 256>>>(Wx1, pWhi, pWlo, nW4);
    k_gemm_mma<<<ggrid, 256, GSMEM_BYTES>>>();
    k_split<<<(nW4 + 255) / 256, 256>>>(Wh1, pWhi, pWlo, nW4);
    k_recur_mma<<<NB, RNT, RSMEM_BYTES>>>(bx1, bh1, out, 1);

    // Tail
    if (out_size >= Mq * Hq + 4 * Bq * Hq)
        k_final<<<(2 * Bq * Hq + 255) / 256, 256>>>(out);
}

// round 7
// speedup vs baseline: 2.9067x; 1.0020x over previous
#include <cuda_runtime.h>
#include <cuda_bf16.h>
#include <math.h>
#include <stdint.h>

// Problem constants
#define Bq 32
#define Sq 512
#define Dq 1024
#define Hq 1024
#define NG 4096            // 4*H
#define Mq (Bq * Sq)       // 16384

#define NB 128             // persistent CTAs for recurrence
#define RNT 512            // threads per CTA in recurrent kernel

// ---------------------------------------------------------------------------
// Scratch (device globals -- no allocations allowed)
// ---------------------------------------------------------------------------
static __device__ float g_Gx[(size_t)Mq * NG];             // input-side gates
static __device__ float g_H0[(size_t)Mq * Hq];             // layer-0 outputs [b*S+t][H]
static __device__ float g_htf[2][Hq * Bq];                 // final h (t=511) [u*32+b]
static __device__ float g_cst[2][Hq * Bq];                 // final c (t=511) [u*32+b]
static __device__ unsigned g_bar[2];                       // grid barrier counters
static __device__ __nv_bfloat16 g_Ahi[(size_t)Mq * 1024];  // GEMM A hi (x or H0)
static __device__ __nv_bfloat16 g_Alo[(size_t)Mq * 1024];  // GEMM A lo
static __device__ __nv_bfloat16 g_Whi[(size_t)NG * 1024];  // W hi (Wx for GEMM, Wh for recur)
static __device__ __nv_bfloat16 g_Wlo[(size_t)NG * 1024];  // W lo
static __device__ __nv_bfloat16 g_hbh[2][2][Bq * 1024];    // recur h hi [layer][parity][b][k]
static __device__ __nv_bfloat16 g_hbl[2][2][Bq * 1024];    // recur h lo

// ---------------------------------------------------------------------------
// Base-ISA tensor helpers (sm_80+ features, valid on sm_103 base target)
// ---------------------------------------------------------------------------
__device__ __forceinline__ uint32_t smem_to_u32(const void* p) {
    uint32_t a;
    asm("{ .reg .u64 t; cvta.to.shared.u64 t, %1; cvt.u32.u64 %0, t; }" : "=r"(a) : "l"(p));
    return a;
}

#define LDSM_X4(r, addr) \
    asm volatile("ldmatrix.sync.aligned.m8n8.x4.shared.b16 {%0,%1,%2,%3}, [%4];" \
        : "=r"((r)[0]), "=r"((r)[1]), "=r"((r)[2]), "=r"((r)[3]) : "r"(addr))

#define MMA16816(d, a, b0, b1) \
    asm volatile("mma.sync.aligned.m16n8k16.row.col.f32.bf16.bf16.f32 " \
        "{%0,%1,%2,%3}, {%4,%5,%6,%7}, {%8,%9}, {%0,%1,%2,%3};" \
        : "+f"((d)[0]), "+f"((d)[1]), "+f"((d)[2]), "+f"((d)[3]) \
        : "r"((a)[0]), "r"((a)[1]), "r"((a)[2]), "r"((a)[3]), "r"(b0), "r"(b1))

#define CP_ASYNC16(saddr, gptr) \
    asm volatile("cp.async.cg.shared.global [%0], [%1], 16;" :: "r"(saddr), "l"(gptr))
#define CP_COMMIT() asm volatile("cp.async.commit_group;" ::: "memory")
#define CP_WAIT(n)  asm volatile("cp.async.wait_group %0;" :: "n"(n) : "memory")

// ---------------------------------------------------------------------------
// Zero bf16 h state (both layers/parities) + barrier counters
// ---------------------------------------------------------------------------
__global__ void k_zero_state() {
    int i = blockIdx.x * blockDim.x + threadIdx.x;
    int n = 2 * 2 * Bq * 1024 / 2;           // u32 count
    if (i < n) {
        ((uint32_t*)g_hbh)[i] = 0u;
        ((uint32_t*)g_hbl)[i] = 0u;
    }
    if (i == 0) { g_bar[0] = 0u; g_bar[1] = 0u; }
}

// ---------------------------------------------------------------------------
// fp32 -> bf16 (hi, lo) split: hi = rn(f), lo = rn(f - hi)
// ---------------------------------------------------------------------------
__global__ void k_split(const float* __restrict__ src,
                        __nv_bfloat16* __restrict__ hi,
                        __nv_bfloat16* __restrict__ lo, int n4)
{
    int i = blockIdx.x * blockDim.x + threadIdx.x;
    if (i >= n4) return;
    float4 v = ((const float4*)src)[i];
    __nv_bfloat16 h0 = __float2bfloat16(v.x), h1 = __float2bfloat16(v.y);
    __nv_bfloat16 h2 = __float2bfloat16(v.z), h3 = __float2bfloat16(v.w);
    __nv_bfloat16 l0 = __float2bfloat16(v.x - __bfloat162float(h0));
    __nv_bfloat16 l1 = __float2bfloat16(v.y - __bfloat162float(h1));
    __nv_bfloat16 l2 = __float2bfloat16(v.z - __bfloat162float(h2));
    __nv_bfloat16 l3 = __float2bfloat16(v.w - __bfloat162float(h3));
    ((__nv_bfloat162*)hi)[i * 2 + 0] = __nv_bfloat162(h0, h1);
    ((__nv_bfloat162*)hi)[i * 2 + 1] = __nv_bfloat162(h2, h3);
    ((__nv_bfloat162*)lo)[i * 2 + 0] = __nv_bfloat162(l0, l1);
    ((__nv_bfloat162*)lo)[i * 2 + 1] = __nv_bfloat162(l2, l3);
}

// ---------------------------------------------------------------------------
// Tensor-core GEMM via mma.sync:
//   g_Gx[M,4096] = (Ahi+Alo)[M,1024] @ (Whi+Wlo)[4096,1024]^T  (3-term)
// CTA tile 128x128, BK=64 (16 chunks x 4 kk), cp.async double buffer.
// Tile stride 72 halves (64 + 8 pad).
// ---------------------------------------------------------------------------
#define TILE_H   (128 * 72)                 // halves per tile
#define GBUF_BYTES (4 * TILE_H * 2)         // 73728
#define GSMEM_BYTES (2 * GBUF_BYTES)        // 147456

__global__ __launch_bounds__(256, 1) void k_gemm_mma()
{
    extern __shared__ __align__(16) char smem[];
    uint32_t sm_base = smem_to_u32(smem);
    int tid = threadIdx.x;
    int bn = blockIdx.x * 128;
    int bm = blockIdx.y * 128;
    int lane = tid & 31;
    int wid = tid >> 5;
    int wm = (wid & 1) * 64;
    int wn = (wid >> 1) * 32;

    const __nv_bfloat16* gsrc[4];
    gsrc[0] = g_Ahi + (size_t)bm * 1024;
    gsrc[1] = g_Alo + (size_t)bm * 1024;
    gsrc[2] = g_Whi + (size_t)bn * 1024;
    gsrc[3] = g_Wlo + (size_t)bn * 1024;

    float acc[4][4][4];
#pragma unroll
    for (int i = 0; i < 4; i++)
#pragma unroll
        for (int j = 0; j < 4; j++)
#pragma unroll
            for (int k = 0; k < 4; k++) acc[i][j][k] = 0.f;

    int row_a = lane & 15;
    int kh_a  = lane >> 4;
    int row_b = (lane & 7) + ((lane >> 4) << 3);
    int kh_b  = (lane >> 3) & 1;

#define ISSUE_CHUNK(ch) do {                                                   \
    int _k0 = (ch) * 64;                                                       \
    uint32_t _sb = sm_base + ((ch) & 1) * GBUF_BYTES;                          \
    _Pragma("unroll")                                                          \
    for (int _r = 0; _r < 16; _r++) {                                          \
        int _id = tid + _r * 256;                                              \
        int _tile = _id >> 10;                                                 \
        int _row = (_id >> 3) & 127;                                           \
        int _k8 = (_id & 7) * 8;                                               \
        CP_ASYNC16(_sb + (uint32_t)(_tile * TILE_H + _row * 72 + _k8) * 2,     \
                   gsrc[_tile] + (size_t)_row * 1024 + _k0 + _k8);             \
    }                                                                          \
    CP_COMMIT();                                                               \
} while (0)

    ISSUE_CHUNK(0);

    for (int ch = 0; ch < 16; ch++) {
        if (ch + 1 < 16) { ISSUE_CHUNK(ch + 1); CP_WAIT(1); }
        else             { CP_WAIT(0); }
        __syncthreads();

        uint32_t sb = sm_base + (ch & 1) * GBUF_BYTES;
        uint32_t ah_t = sb;
        uint32_t al_t = sb + TILE_H * 2;
        uint32_t wh_t = sb + 2 * TILE_H * 2;
        uint32_t wl_t = sb + 3 * TILE_H * 2;

#pragma unroll
        for (int kk = 0; kk < 4; kk++) {
            uint32_t ah[4][4], al[4][4], wh[2][4], wl[2][4];
#pragma unroll
            for (int mi = 0; mi < 4; mi++) {
                uint32_t off = (uint32_t)((wm + mi * 16 + row_a) * 72 + kk * 16 + kh_a * 8) * 2;
                LDSM_X4(ah[mi], ah_t + off);
                LDSM_X4(al[mi], al_t + off);
            }
#pragma unroll
            for (int p = 0; p < 2; p++) {
                uint32_t off = (uint32_t)((wn + p * 16 + row_b) * 72 + kk * 16 + kh_b * 8) * 2;
                LDSM_X4(wh[p], wh_t + off);
                LDSM_X4(wl[p], wl_t + off);
            }
#pragma unroll
            for (int mi = 0; mi < 4; mi++)
#pragma unroll
                for (int ni = 0; ni < 4; ni++) {
                    int pr = ni >> 1, sb2 = (ni & 1) * 2;
                    MMA16816(acc[mi][ni], ah[mi], wh[pr][sb2], wh[pr][sb2 + 1]);
                    MMA16816(acc[mi][ni], ah[mi], wl[pr][sb2], wl[pr][sb2 + 1]);
                    MMA16816(acc[mi][ni], al[mi], wh[pr][sb2], wh[pr][sb2 + 1]);
                }
        }
        __syncthreads();
    }
#undef ISSUE_CHUNK

    int g = lane >> 2, tig = lane & 3;
#pragma unroll
    for (int mi = 0; mi < 4; mi++) {
#pragma unroll
        for (int ni = 0; ni < 4; ni++) {
            int row = bm + wm + mi * 16 + g;
            int col = bn + wn + ni * 8 + tig * 2;
            float2 v0 = make_float2(acc[mi][ni][0], acc[mi][ni][1]);
            float2 v1 = make_float2(acc[mi][ni][2], acc[mi][ni][3]);
            *(float2*)&g_Gx[(size_t)row * NG + col] = v0;
            *(float2*)&g_Gx[(size_t)(row + 8) * NG + col] = v1;
        }
    }
}

// ---------------------------------------------------------------------------
// Tensor-core persistent recurrence (128 CTA x 512 thr).
// CTA bx owns units u0=bx*8..+7 => 32 local gate rows (r = gate*8+uu).
// 16 warps: wid = mi + 2*ks; mi: m-half (16 rows), ks: 128-wide k-slice.
// Wh slice held in A-fragments in REGISTERS for the whole layer.
// Per step: prefetch g_Gx -> cp.async h tiles -> ldmatrix B -> 96 MMA ->
// partials -> 512-thread reduce -> fused LSTM epilogue (c in registers).
// ---------------------------------------------------------------------------
#define HPAD 1032                              // halves per smem row (1024+8)
#define SH_BYTES (Bq * HPAD * 2)               // one h tile (hi or lo): 66048
#define SP_OFF   (2 * SH_BYTES)                // partials offset: 132096
#define SP_BYTES (16 * 16 * 34 * 4)            // [2*8][16][34] f32: 34816
#define SG_OFF   (SP_OFF + SP_BYTES)           // reduced gates G[32][33]
#define SG_BYTES (32 * 33 * 4)                 // 4224
#define SBIAS_OFF (SG_OFF + SG_BYTES)
#define RSMEM_BYTES (SBIAS_OFF + 128)

__global__ __launch_bounds__(RNT, 1) void k_recur_mma(
    const float* __restrict__ b1, const float* __restrict__ b2,
    float* __restrict__ dout, int layer)
{
    extern __shared__ __align__(16) char smem[];
    __nv_bfloat16* sHhi = (__nv_bfloat16*)smem;
    __nv_bfloat16* sHlo = (__nv_bfloat16*)(smem + SH_BYTES);
    float* sP    = (float*)(smem + SP_OFF);
    float* sG    = (float*)(smem + SG_OFF);
    float* sBias = (float*)(smem + SBIAS_OFF);

    int tid  = threadIdx.x;
    int lane = tid & 31;
    int wid  = tid >> 5;
    int mi   = wid & 1;
    int ks   = wid >> 1;
    int u0   = blockIdx.x * 8;

    uint32_t sHhi_u = smem_to_u32(sHhi);
    uint32_t sHlo_u = smem_to_u32(sHlo);

    // ---- prologue: load Wh slice into A-fragments (registers) ----
    uint32_t a_hi[8][4], a_lo[8][4];
    {
        int r = tid >> 4, c16 = tid & 15;
        int jrow = (r >> 3) * Hq + u0 + (r & 7);
        int arow = mi * 16 + (lane & 15);
        int acol8 = (lane >> 4) * 8;
        uint32_t abase = sHhi_u + (uint32_t)(arow * HPAD + acol8) * 2;

        const __nv_bfloat16* wsrc = g_Whi + (size_t)jrow * 1024;
#pragma unroll
        for (int j = 0; j < 8; j++) {
            int cc = c16 + j * 16;
            *(uint4*)(sHhi + r * HPAD + cc * 8) = __ldcg((const uint4*)(wsrc + cc * 8));
        }
        __syncthreads();
#pragma unroll
        for (int kg = 0; kg < 8; kg++)
            LDSM_X4(a_hi[kg], abase + (uint32_t)((ks * 128 + kg * 16) * 2));
        __syncthreads();

        wsrc = g_Wlo + (size_t)jrow * 1024;
#pragma unroll
        for (int j = 0; j < 8; j++) {
            int cc = c16 + j * 16;
            *(uint4*)(sHhi + r * HPAD + cc * 8) = __ldcg((const uint4*)(wsrc + cc * 8));
        }
        __syncthreads();
#pragma unroll
        for (int kg = 0; kg < 8; kg++)
            LDSM_X4(a_lo[kg], abase + (uint32_t)((ks * 128 + kg * 16) * 2));
        __syncthreads();
    }

    if (tid < 32) {
        int jrow = (tid >> 3) * Hq + u0 + (tid & 7);
        sBias[tid] = b1[jrow] + b2[jrow];
    }

    // B-fragment ldmatrix lane addressing ([b][k], stride HPAD)
    int brow  = ((lane >> 4) * 8) + (lane & 7);
    int bcol8 = ((lane >> 3) & 1) * 8;
    uint32_t bh_base0 = sHhi_u + (uint32_t)(brow * HPAD + bcol8) * 2;
    uint32_t bh_base2 = bh_base0 + (uint32_t)(16 * HPAD) * 2;
    uint32_t bl_base0 = sHlo_u + (uint32_t)(brow * HPAD + bcol8) * 2;
    uint32_t bl_base2 = bl_base0 + (uint32_t)(16 * HPAD) * 2;
    uint32_t kslice = (uint32_t)(ks * 128) * 2;

    // epilogue ownership: thread (b, uu), c in register
    int eb = tid >> 3, euu = tid & 7;                // valid for tid<256
    float c_reg = 0.f;

    // reduce-phase ownership: two outputs o=tid, o+512
    int r0 = tid >> 5, b0v = tid & 31;               // output 0: row r0, batch b0v
    int r1 = (tid + 512) >> 5, b1v = b0v;            // output 1: row r0+16

    float* outp = layer ? dout : g_H0;
    int hload_b = tid >> 4, hload_c = tid & 15;

    for (int t = 0; t < Sq; t++) {
        // ---- prefetch input-side gates for this (t, b, u): 4 DRAM loads ----
        float gx[4];
        if (tid < 256) {
            size_t gxb = ((size_t)(eb * Sq + t)) * NG + u0 + euu;
#pragma unroll
            for (int g = 0; g < 4; g++) gx[g] = __ldcg(&g_Gx[gxb + (size_t)g * 1024]);
        }

        // ---- stage h tiles (hi + lo) via cp.async ----
        {
            const __nv_bfloat16* hh = g_hbh[layer][t & 1] + hload_b * 1024;
            const __nv_bfloat16* hl = g_hbl[layer][t & 1] + hload_b * 1024;
            uint32_t dh = sHhi_u + (uint32_t)(hload_b * HPAD) * 2;
            uint32_t dl = sHlo_u + (uint32_t)(hload_b * HPAD) * 2;
#pragma unroll
            for (int j = 0; j < 8; j++) {
                int cc = (hload_c + j * 16) * 8;
                CP_ASYNC16(dh + (uint32_t)cc * 2, hh + cc);
                CP_ASYNC16(dl + (uint32_t)cc * 2, hl + cc);
            }
            CP_COMMIT();
            CP_WAIT(0);
        }
        __syncthreads();

        // ---- 96 MMAs per warp ----
        float acc[4][4];
#pragma unroll
        for (int nf = 0; nf < 4; nf++)
#pragma unroll
            for (int e = 0; e < 4; e++) acc[nf][e] = 0.f;

#pragma unroll
        for (int kg = 0; kg < 8; kg++) {
            uint32_t koff = kslice + (uint32_t)(kg * 16) * 2;
            uint32_t bh[8], bl[8];
            LDSM_X4(&bh[0], bh_base0 + koff);
            LDSM_X4(&bh[4], bh_base2 + koff);
            LDSM_X4(&bl[0], bl_base0 + koff);
            LDSM_X4(&bl[4], bl_base2 + koff);
#pragma unroll
            for (int nf = 0; nf < 4; nf++) {
                MMA16816(acc[nf], a_hi[kg], bh[nf * 2], bh[nf * 2 + 1]);
                MMA16816(acc[nf], a_hi[kg], bl[nf * 2], bl[nf * 2 + 1]);
                MMA16816(acc[nf], a_lo[kg], bh[nf * 2], bh[nf * 2 + 1]);
            }
        }

        // ---- write k-split partials: sP[(mi*8+ks)*16 + r16][34] ----
        {
            int r16 = lane >> 2;
            int colb = (lane & 3) * 2;
            float* base = sP + (size_t)((mi * 8 + ks) * 16) * 34;
#pragma unroll
            for (int nf = 0; nf < 4; nf++) {
                *(float2*)&base[(r16)     * 34 + nf * 8 + colb] = make_float2(acc[nf][0], acc[nf][1]);
                *(float2*)&base[(r16 + 8) * 34 + nf * 8 + colb] = make_float2(acc[nf][2], acc[nf][3]);
            }
        }
        __syncthreads();

        // ---- 512-thread reduction over 8 k-slices (conflict-free, lane=batch) ----
        {
            int m0 = r0 >> 4, q0 = r0 & 15;
            int m1 = r1 >> 4, q1 = r1 & 15;
            float s0 = 0.f, s1 = 0.f;
#pragma unroll
            for (int kss = 0; kss < 8; kss++) {
                s0 += sP[((m0 * 8 + kss) * 16 + q0) * 34 + b0v];
                s1 += sP[((m1 * 8 + kss) * 16 + q1) * 34 + b1v];
            }
            sG[r0 * 33 + b0v] = s0;
            sG[r1 * 33 + b1v] = s1;
        }
        __syncthreads();

        // ---- fused LSTM epilogue (tid<256: thread = (batch eb, unit euu)) ----
        if (tid < 256) {
            float gate[4];
#pragma unroll
            for (int g = 0; g < 4; g++) {
                int r = g * 8 + euu;
                gate[g] = sG[r * 33 + eb] + sBias[r] + gx[g];
            }
            float sf = 1.f / (1.f + __expf(-gate[0]));
            float si = 1.f / (1.f + __expf(-gate[1]));
            float so = 1.f / (1.f + __expf(-gate[3]));
            float cn = sf * c_reg + si * tanhf(gate[2]);
            float hn = so * tanhf(cn);
            c_reg = cn;

            __nv_bfloat16 hhi = __float2bfloat16(hn);
            __nv_bfloat16 hlo = __float2bfloat16(hn - __bfloat162float(hhi));
            int hp = (t + 1) & 1;
            g_hbh[layer][hp][eb * 1024 + u0 + euu] = hhi;
            g_hbl[layer][hp][eb * 1024 + u0 + euu] = hlo;
            outp[((size_t)(eb * Sq + t)) * Hq + u0 + euu] = hn;
            if (t == Sq - 1) {
                int su = (u0 + euu) * Bq + eb;
                g_htf[layer][su] = hn;
                g_cst[layer][su] = cn;
            }
        }

        // ---- grid barrier ----
        __threadfence();
        __syncthreads();
        if (tid == 0) {
            atomicAdd(&g_bar[layer], 1u);
            unsigned target = (unsigned)NB * (unsigned)(t + 1);
            while (*(volatile unsigned*)&g_bar[layer] < target) { }
        }
        __syncthreads();
    }
}

// ---------------------------------------------------------------------------
// Tail: h_n [L,B,H] then c_n [L,B,H] after outputs.
// ---------------------------------------------------------------------------
__global__ void k_final(float* __restrict__ out) {
    int i = blockIdx.x * blockDim.x + threadIdx.x;
    int n = 2 * Bq * Hq;
    if (i < n) {
        int l = i / (Bq * Hq);
        int r = i - l * (Bq * Hq);
        int b = r / Hq;
        int u = r - b * Hq;
        out[(size_t)Mq * Hq + i]     = g_htf[l][u * Bq + b];
        out[(size_t)Mq * Hq + n + i] = g_cst[l][u * Bq + b];
    }
}

// ---------------------------------------------------------------------------
extern "C" void kernel_launch(void* const* d_in, const int* in_sizes, int n_in,
                              void* d_out, int out_size) {
    const float* x   = (const float*)d_in[0];
    const float* Wx0 = (const float*)d_in[1];
    const float* Wh0 = (const float*)d_in[2];
    const float* bx0 = (const float*)d_in[3];
    const float* bh0 = (const float*)d_in[4];
    const float* Wx1 = (const float*)d_in[5];
    const float* Wh1 = (const float*)d_in[6];
    const float* bx1 = (const float*)d_in[7];
    const float* bh1 = (const float*)d_in[8];
    float* out = (float*)d_out;

    cudaFuncSetAttribute(k_gemm_mma,  cudaFuncAttributeMaxDynamicSharedMemorySize, GSMEM_BYTES);
    cudaFuncSetAttribute(k_recur_mma, cudaFuncAttributeMaxDynamicSharedMemorySize, RSMEM_BYTES);

    static __nv_bfloat16 *pAhi = nullptr, *pAlo = nullptr, *pWhi = nullptr, *pWlo = nullptr;
    static float* pH0 = nullptr;
    if (!pAhi) {
        cudaGetSymbolAddress((void**)&pAhi, g_Ahi);
        cudaGetSymbolAddress((void**)&pAlo, g_Alo);
        cudaGetSymbolAddress((void**)&pWhi, g_Whi);
        cudaGetSymbolAddress((void**)&pWlo, g_Wlo);
        cudaGetSymbolAddress((void**)&pH0,  g_H0);
    }

    const int nZ = 2 * 2 * Bq * 1024 / 2;
    k_zero_state<<<(nZ + 255) / 256, 256>>>();

    const int nA4 = Mq * 1024 / 4;
    const int nW4 = NG * 1024 / 4;
    dim3 ggrid(NG / 128, Mq / 128);      // (32, 128)

    // Layer 0
    k_split<<<(nA4 + 255) / 256, 256>>>(x, pAhi, pAlo, nA4);
    k_split<<<(nW4 + 255) / 256, 256>>>(Wx0, pWhi, pWlo, nW4);
    k_gemm_mma<<<ggrid, 256, GSMEM_BYTES>>>();
    k_split<<<(nW4 + 255) / 256, 256>>>(Wh0, pWhi, pWlo, nW4);
    k_recur_mma<<<NB, RNT, RSMEM_BYTES>>>(bx0, bh0, out, 0);

    // Layer 1
    k_split<<<(nA4 + 255) / 256, 256>>>(pH0, pAhi, pAlo, nA4);
    k_split<<<(nW4 + 255) / 256, 256>>>(Wx1, pWhi, pWlo, nW4);
    k_gemm_mma<<<ggrid, 256, GSMEM_BYTES>>>();
    k_split<<<(nW4 + 255) / 256, 256>>>(Wh1, pWhi, pWlo, nW4);
    k_recur_mma<<<NB, RNT, RSMEM_BYTES>>>(bx1, bh1, out, 1);

    // Tail
    if (out_size >= Mq * Hq + 4 * Bq * Hq)
        k_final<<<(2 * Bq * Hq + 255) / 256, 256>>>(out);
}

// round 8
// speedup vs baseline: 4.7820x; 1.6452x over previous
#include <cuda_runtime.h>
#include <cuda_bf16.h>
#include <cuda_fp16.h>
#include <math.h>
#include <stdint.h>

// Problem constants
#define Bq 32
#define Sq 512
#define Dq 1024
#define Hq 1024
#define NG 4096            // 4*H
#define Mq (Bq * Sq)       // 16384

#define NB 128             // persistent CTAs for recurrence
#define RNT 512            // threads per CTA in recurrent kernel

// ---------------------------------------------------------------------------
// Scratch (device globals -- no allocations allowed)
// ---------------------------------------------------------------------------
static __device__ float g_Gx[(size_t)Mq * NG];             // input-side gates
static __device__ float g_H0[(size_t)Mq * Hq];             // layer-0 outputs [b*S+t][H]
static __device__ float g_htf[2][Hq * Bq];                 // final h (t=511) [u*32+b]
static __device__ float g_cst[2][Hq * Bq];                 // final c (t=511) [u*32+b]
static __device__ unsigned g_bar[2];                       // grid barrier counters
static __device__ __nv_bfloat16 g_Ahi[(size_t)Mq * 1024];  // GEMM A hi (x or H0)
static __device__ __nv_bfloat16 g_Alo[(size_t)Mq * 1024];  // GEMM A lo
static __device__ __nv_bfloat16 g_Whi[(size_t)NG * 1024];  // GEMM W hi (Wx)
static __device__ __nv_bfloat16 g_Wlo[(size_t)NG * 1024];  // GEMM W lo
static __device__ __half g_Fhi[(size_t)NG * 1024];         // recur Wh hi (fp16)
static __device__ __half g_Flo[(size_t)NG * 1024];         // recur Wh lo (fp16)
static __device__ __half g_hb[2][2][Bq * 1024];            // recur h fp16 [layer][parity][b][k]

// ---------------------------------------------------------------------------
// Base-ISA tensor helpers (sm_80+ features, valid on sm_103 base target)
// ---------------------------------------------------------------------------
__device__ __forceinline__ uint32_t smem_to_u32(const void* p) {
    uint32_t a;
    asm("{ .reg .u64 t; cvta.to.shared.u64 t, %1; cvt.u32.u64 %0, t; }" : "=r"(a) : "l"(p));
    return a;
}

#define LDSM_X4(r, addr) \
    asm volatile("ldmatrix.sync.aligned.m8n8.x4.shared.b16 {%0,%1,%2,%3}, [%4];" \
        : "=r"((r)[0]), "=r"((r)[1]), "=r"((r)[2]), "=r"((r)[3]) : "r"(addr))

#define MMA16816_BF(d, a, b0, b1) \
    asm volatile("mma.sync.aligned.m16n8k16.row.col.f32.bf16.bf16.f32 " \
        "{%0,%1,%2,%3}, {%4,%5,%6,%7}, {%8,%9}, {%0,%1,%2,%3};" \
        : "+f"((d)[0]), "+f"((d)[1]), "+f"((d)[2]), "+f"((d)[3]) \
        : "r"((a)[0]), "r"((a)[1]), "r"((a)[2]), "r"((a)[3]), "r"(b0), "r"(b1))

#define MMA16816_FP(d, a, b0, b1) \
    asm volatile("mma.sync.aligned.m16n8k16.row.col.f32.f16.f16.f32 " \
        "{%0,%1,%2,%3}, {%4,%5,%6,%7}, {%8,%9}, {%0,%1,%2,%3};" \
        : "+f"((d)[0]), "+f"((d)[1]), "+f"((d)[2]), "+f"((d)[3]) \
        : "r"((a)[0]), "r"((a)[1]), "r"((a)[2]), "r"((a)[3]), "r"(b0), "r"(b1))

#define CP_ASYNC16(saddr, gptr) \
    asm volatile("cp.async.cg.shared.global [%0], [%1], 16;" :: "r"(saddr), "l"(gptr))
#define CP_COMMIT() asm volatile("cp.async.commit_group;" ::: "memory")
#define CP_WAIT(n)  asm volatile("cp.async.wait_group %0;" :: "n"(n) : "memory")

// ---------------------------------------------------------------------------
// Zero fp16 h state + barrier counters
// ---------------------------------------------------------------------------
__global__ void k_zero_state() {
    int i = blockIdx.x * blockDim.x + threadIdx.x;
    int n = 2 * 2 * Bq * 1024 / 2;           // u32 count
    if (i < n) ((uint32_t*)g_hb)[i] = 0u;
    if (i == 0) { g_bar[0] = 0u; g_bar[1] = 0u; }
}

// ---------------------------------------------------------------------------
// fp32 -> bf16 (hi, lo) split (GEMM operands)
// ---------------------------------------------------------------------------
__global__ void k_split(const float* __restrict__ src,
                        __nv_bfloat16* __restrict__ hi,
                        __nv_bfloat16* __restrict__ lo, int n4)
{
    int i = blockIdx.x * blockDim.x + threadIdx.x;
    if (i >= n4) return;
    float4 v = ((const float4*)src)[i];
    __nv_bfloat16 h0 = __float2bfloat16(v.x), h1 = __float2bfloat16(v.y);
    __nv_bfloat16 h2 = __float2bfloat16(v.z), h3 = __float2bfloat16(v.w);
    __nv_bfloat16 l0 = __float2bfloat16(v.x - __bfloat162float(h0));
    __nv_bfloat16 l1 = __float2bfloat16(v.y - __bfloat162float(h1));
    __nv_bfloat16 l2 = __float2bfloat16(v.z - __bfloat162float(h2));
    __nv_bfloat16 l3 = __float2bfloat16(v.w - __bfloat162float(h3));
    ((__nv_bfloat162*)hi)[i * 2 + 0] = __nv_bfloat162(h0, h1);
    ((__nv_bfloat162*)hi)[i * 2 + 1] = __nv_bfloat162(h2, h3);
    ((__nv_bfloat162*)lo)[i * 2 + 0] = __nv_bfloat162(l0, l1);
    ((__nv_bfloat162*)lo)[i * 2 + 1] = __nv_bfloat162(l2, l3);
}

// ---------------------------------------------------------------------------
// fp32 -> fp16 (hi, lo) split (recurrent weights)
// ---------------------------------------------------------------------------
__global__ void k_split_f16(const float* __restrict__ src,
                            __half* __restrict__ hi,
                            __half* __restrict__ lo, int n4)
{
    int i = blockIdx.x * blockDim.x + threadIdx.x;
    if (i >= n4) return;
    float4 v = ((const float4*)src)[i];
    __half h0 = __float2half_rn(v.x), h1 = __float2half_rn(v.y);
    __half h2 = __float2half_rn(v.z), h3 = __float2half_rn(v.w);
    __half l0 = __float2half_rn(v.x - __half2float(h0));
    __half l1 = __float2half_rn(v.y - __half2float(h1));
    __half l2 = __float2half_rn(v.z - __half2float(h2));
    __half l3 = __float2half_rn(v.w - __half2float(h3));
    ((__half2*)hi)[i * 2 + 0] = __halves2half2(h0, h1);
    ((__half2*)hi)[i * 2 + 1] = __halves2half2(h2, h3);
    ((__half2*)lo)[i * 2 + 0] = __halves2half2(l0, l1);
    ((__half2*)lo)[i * 2 + 1] = __halves2half2(l2, l3);
}

// ---------------------------------------------------------------------------
// Tensor-core GEMM via mma.sync (verified, unchanged):
//   g_Gx[M,4096] = (Ahi+Alo)[M,1024] @ (Whi+Wlo)[4096,1024]^T  (3-term bf16)
// ---------------------------------------------------------------------------
#define TILE_H   (128 * 72)
#define GBUF_BYTES (4 * TILE_H * 2)
#define GSMEM_BYTES (2 * GBUF_BYTES)

__global__ __launch_bounds__(256, 1) void k_gemm_mma()
{
    extern __shared__ __align__(16) char smem[];
    uint32_t sm_base = smem_to_u32(smem);
    int tid = threadIdx.x;
    int bn = blockIdx.x * 128;
    int bm = blockIdx.y * 128;
    int lane = tid & 31;
    int wid = tid >> 5;
    int wm = (wid & 1) * 64;
    int wn = (wid >> 1) * 32;

    const __nv_bfloat16* gsrc[4];
    gsrc[0] = g_Ahi + (size_t)bm * 1024;
    gsrc[1] = g_Alo + (size_t)bm * 1024;
    gsrc[2] = g_Whi + (size_t)bn * 1024;
    gsrc[3] = g_Wlo + (size_t)bn * 1024;

    float acc[4][4][4];
#pragma unroll
    for (int i = 0; i < 4; i++)
#pragma unroll
        for (int j = 0; j < 4; j++)
#pragma unroll
            for (int k = 0; k < 4; k++) acc[i][j][k] = 0.f;

    int row_a = lane & 15;
    int kh_a  = lane >> 4;
    int row_b = (lane & 7) + ((lane >> 4) << 3);
    int kh_b  = (lane >> 3) & 1;

#define ISSUE_CHUNK(ch) do {                                                   \
    int _k0 = (ch) * 64;                                                       \
    uint32_t _sb = sm_base + ((ch) & 1) * GBUF_BYTES;                          \
    _Pragma("unroll")                                                          \
    for (int _r = 0; _r < 16; _r++) {                                          \
        int _id = tid + _r * 256;                                              \
        int _tile = _id >> 10;                                                 \
        int _row = (_id >> 3) & 127;                                           \
        int _k8 = (_id & 7) * 8;                                               \
        CP_ASYNC16(_sb + (uint32_t)(_tile * TILE_H + _row * 72 + _k8) * 2,     \
                   gsrc[_tile] + (size_t)_row * 1024 + _k0 + _k8);             \
    }                                                                          \
    CP_COMMIT();                                                               \
} while (0)

    ISSUE_CHUNK(0);

    for (int ch = 0; ch < 16; ch++) {
        if (ch + 1 < 16) { ISSUE_CHUNK(ch + 1); CP_WAIT(1); }
        else             { CP_WAIT(0); }
        __syncthreads();

        uint32_t sb = sm_base + (ch & 1) * GBUF_BYTES;
        uint32_t ah_t = sb;
        uint32_t al_t = sb + TILE_H * 2;
        uint32_t wh_t = sb + 2 * TILE_H * 2;
        uint32_t wl_t = sb + 3 * TILE_H * 2;

#pragma unroll
        for (int kk = 0; kk < 4; kk++) {
            uint32_t ah[4][4], al[4][4], wh[2][4], wl[2][4];
#pragma unroll
            for (int mi = 0; mi < 4; mi++) {
                uint32_t off = (uint32_t)((wm + mi * 16 + row_a) * 72 + kk * 16 + kh_a * 8) * 2;
                LDSM_X4(ah[mi], ah_t + off);
                LDSM_X4(al[mi], al_t + off);
            }
#pragma unroll
            for (int p = 0; p < 2; p++) {
                uint32_t off = (uint32_t)((wn + p * 16 + row_b) * 72 + kk * 16 + kh_b * 8) * 2;
                LDSM_X4(wh[p], wh_t + off);
                LDSM_X4(wl[p], wl_t + off);
            }
#pragma unroll
            for (int mi = 0; mi < 4; mi++)
#pragma unroll
                for (int ni = 0; ni < 4; ni++) {
                    int pr = ni >> 1, sb2 = (ni & 1) * 2;
                    MMA16816_BF(acc[mi][ni], ah[mi], wh[pr][sb2], wh[pr][sb2 + 1]);
                    MMA16816_BF(acc[mi][ni], ah[mi], wl[pr][sb2], wl[pr][sb2 + 1]);
                    MMA16816_BF(acc[mi][ni], al[mi], wh[pr][sb2], wh[pr][sb2 + 1]);
                }
        }
        __syncthreads();
    }
#undef ISSUE_CHUNK

    int g = lane >> 2, tig = lane & 3;
#pragma unroll
    for (int mi = 0; mi < 4; mi++) {
#pragma unroll
        for (int ni = 0; ni < 4; ni++) {
            int row = bm + wm + mi * 16 + g;
            int col = bn + wn + ni * 8 + tig * 2;
            float2 v0 = make_float2(acc[mi][ni][0], acc[mi][ni][1]);
            float2 v1 = make_float2(acc[mi][ni][2], acc[mi][ni][3]);
            *(float2*)&g_Gx[(size_t)row * NG + col] = v0;
            *(float2*)&g_Gx[(size_t)(row + 8) * NG + col] = v1;
        }
    }
}

// ---------------------------------------------------------------------------
// Tensor-core persistent recurrence, fp16 2-term:
//   gates = (Fhi + Flo) @ h_fp16  -- 64 MMAs/warp (was 96), h tile 64KB.
// 128 CTA x 512 thr; CTA owns 8 units (32 gate rows); 16 warps (mi, ks).
// Wh slice in registers; h single-fp16 exchanged through L2.
// ---------------------------------------------------------------------------
#define HPAD 1032                              // halves per smem row (1024+8)
#define SH_BYTES (Bq * HPAD * 2)               // h tile: 66048
#define SP_OFF   SH_BYTES
#define SP_BYTES (16 * 16 * 34 * 4)            // [2*8][16][34] f32: 34816
#define SG_OFF   (SP_OFF + SP_BYTES)
#define SG_BYTES (32 * 33 * 4)
#define SBIAS_OFF (SG_OFF + SG_BYTES)
#define RSMEM_BYTES (SBIAS_OFF + 128)          // ~105.4KB

__global__ __launch_bounds__(RNT, 1) void k_recur_mma(
    const float* __restrict__ b1, const float* __restrict__ b2,
    float* __restrict__ dout, int layer)
{
    extern __shared__ __align__(16) char smem[];
    __half* sH   = (__half*)smem;
    float* sP    = (float*)(smem + SP_OFF);
    float* sG    = (float*)(smem + SG_OFF);
    float* sBias = (float*)(smem + SBIAS_OFF);

    int tid  = threadIdx.x;
    int lane = tid & 31;
    int wid  = tid >> 5;
    int mi   = wid & 1;
    int ks   = wid >> 1;
    int u0   = blockIdx.x * 8;

    uint32_t sH_u = smem_to_u32(sH);

    // ---- prologue: load Wh slice (fp16 hi/lo) into A-fragments ----
    uint32_t a_hi[8][4], a_lo[8][4];
    {
        int r = tid >> 4, c16 = tid & 15;
        int jrow = (r >> 3) * Hq + u0 + (r & 7);
        int arow = mi * 16 + (lane & 15);
        int acol8 = (lane >> 4) * 8;
        uint32_t abase = sH_u + (uint32_t)(arow * HPAD + acol8) * 2;

        const __half* wsrc = g_Fhi + (size_t)jrow * 1024;
#pragma unroll
        for (int j = 0; j < 8; j++) {
            int cc = c16 + j * 16;
            *(uint4*)(sH + r * HPAD + cc * 8) = __ldcg((const uint4*)(wsrc + cc * 8));
        }
        __syncthreads();
#pragma unroll
        for (int kg = 0; kg < 8; kg++)
            LDSM_X4(a_hi[kg], abase + (uint32_t)((ks * 128 + kg * 16) * 2));
        __syncthreads();

        wsrc = g_Flo + (size_t)jrow * 1024;
#pragma unroll
        for (int j = 0; j < 8; j++) {
            int cc = c16 + j * 16;
            *(uint4*)(sH + r * HPAD + cc * 8) = __ldcg((const uint4*)(wsrc + cc * 8));
        }
        __syncthreads();
#pragma unroll
        for (int kg = 0; kg < 8; kg++)
            LDSM_X4(a_lo[kg], abase + (uint32_t)((ks * 128 + kg * 16) * 2));
        __syncthreads();
    }

    if (tid < 32) {
        int jrow = (tid >> 3) * Hq + u0 + (tid & 7);
        sBias[tid] = b1[jrow] + b2[jrow];
    }

    // B-fragment ldmatrix lane addressing ([b][k], stride HPAD)
    int brow  = ((lane >> 4) * 8) + (lane & 7);
    int bcol8 = ((lane >> 3) & 1) * 8;
    uint32_t bh_base0 = sH_u + (uint32_t)(brow * HPAD + bcol8) * 2;
    uint32_t bh_base2 = bh_base0 + (uint32_t)(16 * HPAD) * 2;
    uint32_t kslice = (uint32_t)(ks * 128) * 2;

    // epilogue ownership: thread (b, uu), c in register
    int eb = tid >> 3, euu = tid & 7;                // valid for tid<256
    float c_reg = 0.f;

    // reduce-phase ownership
    int r0 = tid >> 5, b0v = tid & 31;
    int r1 = (tid + 512) >> 5;

    float* outp = layer ? dout : g_H0;
    int hload_b = tid >> 4, hload_c = tid & 15;
    size_t gx_base = ((size_t)(eb * Sq)) * NG + u0 + euu;   // + t*NG per step

    // prefetch gates for t=0
    float gx[4];
    if (tid < 256) {
#pragma unroll
        for (int g = 0; g < 4; g++) gx[g] = __ldcg(&g_Gx[gx_base + (size_t)g * 1024]);
    }

    for (int t = 0; t < Sq; t++) {
        // ---- stage h tile (fp16, 64KB) via cp.async ----
        {
            const __half* hh = g_hb[layer][t & 1] + hload_b * 1024;
            uint32_t dh = sH_u + (uint32_t)(hload_b * HPAD) * 2;
#pragma unroll
            for (int j = 0; j < 8; j++) {
                int cc = (hload_c + j * 16) * 8;
                CP_ASYNC16(dh + (uint32_t)cc * 2, hh + cc);
            }
            CP_COMMIT();
            CP_WAIT(0);
        }
        __syncthreads();

        // ---- 64 MMAs per warp (2-term fp16) ----
        float acc[4][4];
#pragma unroll
        for (int nf = 0; nf < 4; nf++)
#pragma unroll
            for (int e = 0; e < 4; e++) acc[nf][e] = 0.f;

#pragma unroll
        for (int kg = 0; kg < 8; kg++) {
            uint32_t koff = kslice + (uint32_t)(kg * 16) * 2;
            uint32_t bh[8];
            LDSM_X4(&bh[0], bh_base0 + koff);
            LDSM_X4(&bh[4], bh_base2 + koff);
#pragma unroll
            for (int nf = 0; nf < 4; nf++) {
                MMA16816_FP(acc[nf], a_hi[kg], bh[nf * 2], bh[nf * 2 + 1]);
                MMA16816_FP(acc[nf], a_lo[kg], bh[nf * 2], bh[nf * 2 + 1]);
            }
        }

        // ---- write k-split partials ----
        {
            int r16 = lane >> 2;
            int colb = (lane & 3) * 2;
            float* base = sP + (size_t)((mi * 8 + ks) * 16) * 34;
#pragma unroll
            for (int nf = 0; nf < 4; nf++) {
                *(float2*)&base[(r16)     * 34 + nf * 8 + colb] = make_float2(acc[nf][0], acc[nf][1]);
                *(float2*)&base[(r16 + 8) * 34 + nf * 8 + colb] = make_float2(acc[nf][2], acc[nf][3]);
            }
        }
        __syncthreads();

        // ---- 512-thread reduction over 8 k-slices ----
        {
            int m0 = r0 >> 4, q0 = r0 & 15;
            int m1 = r1 >> 4, q1 = r1 & 15;
            float s0 = 0.f, s1 = 0.f;
#pragma unroll
            for (int kss = 0; kss < 8; kss++) {
                s0 += sP[((m0 * 8 + kss) * 16 + q0) * 34 + b0v];
                s1 += sP[((m1 * 8 + kss) * 16 + q1) * 34 + b0v];
            }
            sG[r0 * 33 + b0v] = s0;
            sG[r1 * 33 + b0v] = s1;
        }
        __syncthreads();

        // ---- fused LSTM epilogue ----
        if (tid < 256) {
            float gate[4];
#pragma unroll
            for (int g = 0; g < 4; g++) {
                int r = g * 8 + euu;
                gate[g] = sG[r * 33 + eb] + sBias[r] + gx[g];
            }
            float sf = 1.f / (1.f + __expf(-gate[0]));
            float si = 1.f / (1.f + __expf(-gate[1]));
            float so = 1.f / (1.f + __expf(-gate[3]));
            float cn = sf * c_reg + si * tanhf(gate[2]);
            float hn = so * tanhf(cn);
            c_reg = cn;

            int hp = (t + 1) & 1;
            g_hb[layer][hp][eb * 1024 + u0 + euu] = __float2half_rn(hn);
            outp[((size_t)(eb * Sq + t)) * Hq + u0 + euu] = hn;
            if (t == Sq - 1) {
                int su = (u0 + euu) * Bq + eb;
                g_htf[layer][su] = hn;
                g_cst[layer][su] = cn;
            }
            // prefetch next step's input-side gates (hidden behind the barrier)
            if (t + 1 < Sq) {
                size_t gb = gx_base + (size_t)(t + 1) * NG;
#pragma unroll
                for (int g = 0; g < 4; g++) gx[g] = __ldcg(&g_Gx[gb + (size_t)g * 1024]);
            }
        }

        // ---- grid barrier ----
        __threadfence();
        __syncthreads();
        if (tid == 0) {
            atomicAdd(&g_bar[layer], 1u);
            unsigned target = (unsigned)NB * (unsigned)(t + 1);
            while (*(volatile unsigned*)&g_bar[layer] < target) { }
        }
        __syncthreads();
    }
}

// ---------------------------------------------------------------------------
// Tail: h_n [L,B,H] then c_n [L,B,H] after outputs.
// ---------------------------------------------------------------------------
__global__ void k_final(float* __restrict__ out) {
    int i = blockIdx.x * blockDim.x + threadIdx.x;
    int n = 2 * Bq * Hq;
    if (i < n) {
        int l = i / (Bq * Hq);
        int r = i - l * (Bq * Hq);
        int b = r / Hq;
        int u = r - b * Hq;
        out[(size_t)Mq * Hq + i]     = g_htf[l][u * Bq + b];
        out[(size_t)Mq * Hq + n + i] = g_cst[l][u * Bq + b];
    }
}

// ---------------------------------------------------------------------------
extern "C" void kernel_launch(void* const* d_in, const int* in_sizes, int n_in,
                              void* d_out, int out_size) {
    const float* x   = (const float*)d_in[0];
    const float* Wx0 = (const float*)d_in[1];
    const float* Wh0 = (const float*)d_in[2];
    const float* bx0 = (const float*)d_in[3];
    const float* bh0 = (const float*)d_in[4];
    const float* Wx1 = (const float*)d_in[5];
    const float* Wh1 = (const float*)d_in[6];
    const float* bx1 = (const float*)d_in[7];
    const float* bh1 = (const float*)d_in[8];
    float* out = (float*)d_out;

    cudaFuncSetAttribute(k_gemm_mma,  cudaFuncAttributeMaxDynamicSharedMemorySize, GSMEM_BYTES);
    cudaFuncSetAttribute(k_recur_mma, cudaFuncAttributeMaxDynamicSharedMemorySize, RSMEM_BYTES);

    static __nv_bfloat16 *pAhi = nullptr, *pAlo = nullptr, *pWhi = nullptr, *pWlo = nullptr;
    static __half *pFhi = nullptr, *pFlo = nullptr;
    static float* pH0 = nullptr;
    if (!pAhi) {
        cudaGetSymbolAddress((void**)&pAhi, g_Ahi);
        cudaGetSymbolAddress((void**)&pAlo, g_Alo);
        cudaGetSymbolAddress((void**)&pWhi, g_Whi);
        cudaGetSymbolAddress((void**)&pWlo, g_Wlo);
        cudaGetSymbolAddress((void**)&pFhi, g_Fhi);
        cudaGetSymbolAddress((void**)&pFlo, g_Flo);
        cudaGetSymbolAddress((void**)&pH0,  g_H0);
    }

    const int nZ = 2 * 2 * Bq * 1024 / 2;
    k_zero_state<<<(nZ + 255) / 256, 256>>>();

    const int nA4 = Mq * 1024 / 4;
    const int nW4 = NG * 1024 / 4;
    dim3 ggrid(NG / 128, Mq / 128);      // (32, 128)

    // Layer 0
    k_split<<<(nA4 + 255) / 256, 256>>>(x, pAhi, pAlo, nA4);
    k_split<<<(nW4 + 255) / 256, 256>>>(Wx0, pWhi, pWlo, nW4);
    k_gemm_mma<<<ggrid, 256, GSMEM_BYTES>>>();
    k_split_f16<<<(nW4 + 255) / 256, 256>>>(Wh0, pFhi, pFlo, nW4);
    k_recur_mma<<<NB, RNT, RSMEM_BYTES>>>(bx0, bh0, out, 0);

    // Layer 1
    k_split<<<(nA4 + 255) / 256, 256>>>(pH0, pAhi, pAlo, nA4);
    k_split<<<(nW4 + 255) / 256, 256>>>(Wx1, pWhi, pWlo, nW4);
    k_gemm_mma<<<ggrid, 256, GSMEM_BYTES>>>();
    k_split_f16<<<(nW4 + 255) / 256, 256>>>(Wh1, pFhi, pFlo, nW4);
    k_recur_mma<<<NB, RNT, RSMEM_BYTES>>>(bx1, bh1, out, 1);

    // Tail
    if (out_size >= Mq * Hq + 4 * Bq * Hq)
        k_final<<<(2 * Bq * Hq + 255) / 256, 256>>>(out);
}

// round 9
// speedup vs baseline: 5.5360x; 1.1577x over previous
#include <cuda_runtime.h>
#include <cuda_bf16.h>
#include <cuda_fp16.h>
#include <math.h>
#include <stdint.h>

// Problem constants
#define Bq 32
#define Sq 512
#define Dq 1024
#define Hq 1024
#define NG 4096            // 4*H
#define Mq (Bq * Sq)       // 16384

#define NB 128             // persistent CTAs for recurrence
#define RNT 512            // threads per CTA in recurrent kernel

// ---------------------------------------------------------------------------
// Scratch (device globals -- no allocations allowed)
// ---------------------------------------------------------------------------
static __device__ float g_Gx[(size_t)Mq * NG];             // input-side gates
static __device__ float g_htf[2][Hq * Bq];                 // final h (t=511) [u*32+b]
static __device__ float g_cst[2][Hq * Bq];                 // final c (t=511) [u*32+b]
static __device__ unsigned g_bar[2];                       // grid barrier counters
static __device__ __half g_A16x[(size_t)Mq * 1024];        // x as fp16 (GEMM A, layer 0)
static __device__ __half g_A16h[(size_t)Mq * 1024];        // layer-0 h history fp16 (GEMM A, layer 1)
static __device__ __half g_W16h[(size_t)NG * 1024];        // GEMM Wx hi (fp16)
static __device__ __half g_W16l[(size_t)NG * 1024];        // GEMM Wx lo (fp16)
static __device__ __half g_Fh[(size_t)NG * 1024];          // recur Wh (fp16, 1-term)
static __device__ __half g_hb[2][2][Bq * 1024];            // recur h fp16 [layer][parity][b][k]

// ---------------------------------------------------------------------------
// Base-ISA tensor helpers
// ---------------------------------------------------------------------------
__device__ __forceinline__ uint32_t smem_to_u32(const void* p) {
    uint32_t a;
    asm("{ .reg .u64 t; cvta.to.shared.u64 t, %1; cvt.u32.u64 %0, t; }" : "=r"(a) : "l"(p));
    return a;
}

#define LDSM_X4(r, addr) \
    asm volatile("ldmatrix.sync.aligned.m8n8.x4.shared.b16 {%0,%1,%2,%3}, [%4];" \
        : "=r"((r)[0]), "=r"((r)[1]), "=r"((r)[2]), "=r"((r)[3]) : "r"(addr))

#define MMA16816_FP(d, a, b0, b1) \
    asm volatile("mma.sync.aligned.m16n8k16.row.col.f32.f16.f16.f32 " \
        "{%0,%1,%2,%3}, {%4,%5,%6,%7}, {%8,%9}, {%0,%1,%2,%3};" \
        : "+f"((d)[0]), "+f"((d)[1]), "+f"((d)[2]), "+f"((d)[3]) \
        : "r"((a)[0]), "r"((a)[1]), "r"((a)[2]), "r"((a)[3]), "r"(b0), "r"(b1))

#define CP_ASYNC16(saddr, gptr) \
    asm volatile("cp.async.cg.shared.global [%0], [%1], 16;" :: "r"(saddr), "l"(gptr))
#define CP_COMMIT() asm volatile("cp.async.commit_group;" ::: "memory")
#define CP_WAIT(n)  asm volatile("cp.async.wait_group %0;" :: "n"(n) : "memory")

// ---------------------------------------------------------------------------
// Zero fp16 h state + barrier counters
// ---------------------------------------------------------------------------
__global__ void k_zero_state() {
    int i = blockIdx.x * blockDim.x + threadIdx.x;
    int n = 2 * 2 * Bq * 1024 / 2;           // u32 count
    if (i < n) ((uint32_t*)g_hb)[i] = 0u;
    if (i == 0) { g_bar[0] = 0u; g_bar[1] = 0u; }
}

// ---------------------------------------------------------------------------
// fp32 -> fp16 single (rn)
// ---------------------------------------------------------------------------
__global__ void k_tof16(const float* __restrict__ src, __half* __restrict__ dst, int n4) {
    int i = blockIdx.x * blockDim.x + threadIdx.x;
    if (i >= n4) return;
    float4 v = ((const float4*)src)[i];
    ((__half2*)dst)[i * 2 + 0] = __halves2half2(__float2half_rn(v.x), __float2half_rn(v.y));
    ((__half2*)dst)[i * 2 + 1] = __halves2half2(__float2half_rn(v.z), __float2half_rn(v.w));
}

// ---------------------------------------------------------------------------
// fp32 -> fp16 (hi, lo) split (GEMM weights)
// ---------------------------------------------------------------------------
__global__ void k_split_f16(const float* __restrict__ src,
                            __half* __restrict__ hi,
                            __half* __restrict__ lo, int n4)
{
    int i = blockIdx.x * blockDim.x + threadIdx.x;
    if (i >= n4) return;
    float4 v = ((const float4*)src)[i];
    __half h0 = __float2half_rn(v.x), h1 = __float2half_rn(v.y);
    __half h2 = __float2half_rn(v.z), h3 = __float2half_rn(v.w);
    __half l0 = __float2half_rn(v.x - __half2float(h0));
    __half l1 = __float2half_rn(v.y - __half2float(h1));
    __half l2 = __float2half_rn(v.z - __half2float(h2));
    __half l3 = __float2half_rn(v.w - __half2float(h3));
    ((__half2*)hi)[i * 2 + 0] = __halves2half2(h0, h1);
    ((__half2*)hi)[i * 2 + 1] = __halves2half2(h2, h3);
    ((__half2*)lo)[i * 2 + 0] = __halves2half2(l0, l1);
    ((__half2*)lo)[i * 2 + 1] = __halves2half2(l2, l3);
}

// ---------------------------------------------------------------------------
// Tensor-core GEMM (fp16, 2-term):
//   g_Gx[M,4096] = A16[M,1024] @ (W16h+W16l)[4096,1024]^T
// CTA tile 128x128, BK=64, 3 smem tiles (A, Wh, Wl), cp.async double buffer.
// ---------------------------------------------------------------------------
#define GT_H   (128 * 72)                   // halves per tile
#define GBUF_BYTES (3 * GT_H * 2)           // 55296
#define GSMEM_BYTES (2 * GBUF_BYTES)        // 110592

__global__ __launch_bounds__(256, 1) void k_gemm_mma(const __half* __restrict__ A16)
{
    extern __shared__ __align__(16) char smem[];
    uint32_t sm_base = smem_to_u32(smem);
    int tid = threadIdx.x;
    int bn = blockIdx.x * 128;
    int bm = blockIdx.y * 128;
    int lane = tid & 31;
    int wid = tid >> 5;
    int wm = (wid & 1) * 64;
    int wn = (wid >> 1) * 32;

    const __half* gsrc[3];
    gsrc[0] = A16    + (size_t)bm * 1024;
    gsrc[1] = g_W16h + (size_t)bn * 1024;
    gsrc[2] = g_W16l + (size_t)bn * 1024;

    float acc[4][4][4];
#pragma unroll
    for (int i = 0; i < 4; i++)
#pragma unroll
        for (int j = 0; j < 4; j++)
#pragma unroll
            for (int k = 0; k < 4; k++) acc[i][j][k] = 0.f;

    int row_a = lane & 15;
    int kh_a  = lane >> 4;
    int row_b = (lane & 7) + ((lane >> 4) << 3);
    int kh_b  = (lane >> 3) & 1;

#define ISSUE_CHUNK(ch) do {                                                   \
    int _k0 = (ch) * 64;                                                       \
    uint32_t _sb = sm_base + ((ch) & 1) * GBUF_BYTES;                          \
    _Pragma("unroll")                                                          \
    for (int _r = 0; _r < 12; _r++) {                                          \
        int _id = tid + _r * 256;                                              \
        int _tile = _id >> 10;                                                 \
        int _row = (_id >> 3) & 127;                                           \
        int _k8 = (_id & 7) * 8;                                               \
        CP_ASYNC16(_sb + (uint32_t)(_tile * GT_H + _row * 72 + _k8) * 2,       \
                   gsrc[_tile] + (size_t)_row * 1024 + _k0 + _k8);             \
    }                                                                          \
    CP_COMMIT();                                                               \
} while (0)

    ISSUE_CHUNK(0);

    for (int ch = 0; ch < 16; ch++) {
        if (ch + 1 < 16) { ISSUE_CHUNK(ch + 1); CP_WAIT(1); }
        else             { CP_WAIT(0); }
        __syncthreads();

        uint32_t sb = sm_base + (ch & 1) * GBUF_BYTES;
        uint32_t a_t  = sb;
        uint32_t wh_t = sb + GT_H * 2;
        uint32_t wl_t = sb + 2 * GT_H * 2;

#pragma unroll
        for (int kk = 0; kk < 4; kk++) {
            uint32_t af[4][4], wh[2][4], wl[2][4];
#pragma unroll
            for (int mi = 0; mi < 4; mi++) {
                uint32_t off = (uint32_t)((wm + mi * 16 + row_a) * 72 + kk * 16 + kh_a * 8) * 2;
                LDSM_X4(af[mi], a_t + off);
            }
#pragma unroll
            for (int p = 0; p < 2; p++) {
                uint32_t off = (uint32_t)((wn + p * 16 + row_b) * 72 + kk * 16 + kh_b * 8) * 2;
                LDSM_X4(wh[p], wh_t + off);
                LDSM_X4(wl[p], wl_t + off);
            }
#pragma unroll
            for (int mi = 0; mi < 4; mi++)
#pragma unroll
                for (int ni = 0; ni < 4; ni++) {
                    int pr = ni >> 1, sb2 = (ni & 1) * 2;
                    MMA16816_FP(acc[mi][ni], af[mi], wh[pr][sb2], wh[pr][sb2 + 1]);
                    MMA16816_FP(acc[mi][ni], af[mi], wl[pr][sb2], wl[pr][sb2 + 1]);
                }
        }
        __syncthreads();
    }
#undef ISSUE_CHUNK

    int g = lane >> 2, tig = lane & 3;
#pragma unroll
    for (int mi = 0; mi < 4; mi++) {
#pragma unroll
        for (int ni = 0; ni < 4; ni++) {
            int row = bm + wm + mi * 16 + g;
            int col = bn + wn + ni * 8 + tig * 2;
            float2 v0 = make_float2(acc[mi][ni][0], acc[mi][ni][1]);
            float2 v1 = make_float2(acc[mi][ni][2], acc[mi][ni][3]);
            *(float2*)&g_Gx[(size_t)row * NG + col] = v0;
            *(float2*)&g_Gx[(size_t)(row + 8) * NG + col] = v1;
        }
    }
}

// ---------------------------------------------------------------------------
// Tensor-core persistent recurrence, fp16 1-term:
//   gates = Fh @ h_fp16   -- 32 MMAs/warp.
// 128 CTA x 512 thr; CTA owns 8 units (32 gate rows); 16 warps (mi, ks).
// Layer 0 epilogue writes fp16 h history (g_A16h) for layer-1 GEMM.
// ---------------------------------------------------------------------------
#define HPAD 1032                              // halves per smem row (1024+8)
#define SH_BYTES (Bq * HPAD * 2)               // h tile: 66048
#define SP_OFF   SH_BYTES
#define SP_BYTES (16 * 16 * 34 * 4)            // [2*8][16][34] f32: 34816
#define SG_OFF   (SP_OFF + SP_BYTES)
#define SG_BYTES (32 * 33 * 4)
#define SBIAS_OFF (SG_OFF + SG_BYTES)
#define RSMEM_BYTES (SBIAS_OFF + 128)

__global__ __launch_bounds__(RNT, 1) void k_recur_mma(
    const float* __restrict__ b1, const float* __restrict__ b2,
    float* __restrict__ dout, int layer)
{
    extern __shared__ __align__(16) char smem[];
    __half* sH   = (__half*)smem;
    float* sP    = (float*)(smem + SP_OFF);
    float* sG    = (float*)(smem + SG_OFF);
    float* sBias = (float*)(smem + SBIAS_OFF);

    int tid  = threadIdx.x;
    int lane = tid & 31;
    int wid  = tid >> 5;
    int mi   = wid & 1;
    int ks   = wid >> 1;
    int u0   = blockIdx.x * 8;

    uint32_t sH_u = smem_to_u32(sH);

    // ---- prologue: load Wh slice (fp16) into A-fragments ----
    uint32_t a_f[8][4];
    {
        int r = tid >> 4, c16 = tid & 15;
        int jrow = (r >> 3) * Hq + u0 + (r & 7);
        int arow = mi * 16 + (lane & 15);
        int acol8 = (lane >> 4) * 8;
        uint32_t abase = sH_u + (uint32_t)(arow * HPAD + acol8) * 2;

        const __half* wsrc = g_Fh + (size_t)jrow * 1024;
#pragma unroll
        for (int j = 0; j < 8; j++) {
            int cc = c16 + j * 16;
            *(uint4*)(sH + r * HPAD + cc * 8) = __ldcg((const uint4*)(wsrc + cc * 8));
        }
        __syncthreads();
#pragma unroll
        for (int kg = 0; kg < 8; kg++)
            LDSM_X4(a_f[kg], abase + (uint32_t)((ks * 128 + kg * 16) * 2));
        __syncthreads();
    }

    if (tid < 32) {
        int jrow = (tid >> 3) * Hq + u0 + (tid & 7);
        sBias[tid] = b1[jrow] + b2[jrow];
    }

    // B-fragment ldmatrix lane addressing ([b][k], stride HPAD)
    int brow  = ((lane >> 4) * 8) + (lane & 7);
    int bcol8 = ((lane >> 3) & 1) * 8;
    uint32_t bh_base0 = sH_u + (uint32_t)(brow * HPAD + bcol8) * 2;
    uint32_t bh_base2 = bh_base0 + (uint32_t)(16 * HPAD) * 2;
    uint32_t kslice = (uint32_t)(ks * 128) * 2;

    // epilogue ownership: thread (b, uu), c in register
    int eb = tid >> 3, euu = tid & 7;                // valid for tid<256
    float c_reg = 0.f;

    // reduce-phase ownership
    int r0 = tid >> 5, b0v = tid & 31;
    int r1 = (tid + 512) >> 5;

    int hload_b = tid >> 4, hload_c = tid & 15;
    size_t gx_base = ((size_t)(eb * Sq)) * NG + u0 + euu;   // + t*NG per step

    // prefetch gates for t=0
    float gx[4];
    if (tid < 256) {
#pragma unroll
        for (int g = 0; g < 4; g++) gx[g] = __ldcg(&g_Gx[gx_base + (size_t)g * 1024]);
    }

    for (int t = 0; t < Sq; t++) {
        // ---- stage h tile (fp16, 64KB) via cp.async ----
        {
            const __half* hh = g_hb[layer][t & 1] + hload_b * 1024;
            uint32_t dh = sH_u + (uint32_t)(hload_b * HPAD) * 2;
#pragma unroll
            for (int j = 0; j < 8; j++) {
                int cc = (hload_c + j * 16) * 8;
                CP_ASYNC16(dh + (uint32_t)cc * 2, hh + cc);
            }
            CP_COMMIT();
            CP_WAIT(0);
        }
        __syncthreads();

        // ---- 32 MMAs per warp (1-term fp16) ----
        float acc[4][4];
#pragma unroll
        for (int nf = 0; nf < 4; nf++)
#pragma unroll
            for (int e = 0; e < 4; e++) acc[nf][e] = 0.f;

#pragma unroll
        for (int kg = 0; kg < 8; kg++) {
            uint32_t koff = kslice + (uint32_t)(kg * 16) * 2;
            uint32_t bh[8];
            LDSM_X4(&bh[0], bh_base0 + koff);
            LDSM_X4(&bh[4], bh_base2 + koff);
#pragma unroll
            for (int nf = 0; nf < 4; nf++)
                MMA16816_FP(acc[nf], a_f[kg], bh[nf * 2], bh[nf * 2 + 1]);
        }

        // ---- write k-split partials ----
        {
            int r16 = lane >> 2;
            int colb = (lane & 3) * 2;
            float* base = sP + (size_t)((mi * 8 + ks) * 16) * 34;
#pragma unroll
            for (int nf = 0; nf < 4; nf++) {
                *(float2*)&base[(r16)     * 34 + nf * 8 + colb] = make_float2(acc[nf][0], acc[nf][1]);
                *(float2*)&base[(r16 + 8) * 34 + nf * 8 + colb] = make_float2(acc[nf][2], acc[nf][3]);
            }
        }
        __syncthreads();

        // ---- 512-thread reduction over 8 k-slices ----
        {
            int m0 = r0 >> 4, q0 = r0 & 15;
            int m1 = r1 >> 4, q1 = r1 & 15;
            float s0 = 0.f, s1 = 0.f;
#pragma unroll
            for (int kss = 0; kss < 8; kss++) {
                s0 += sP[((m0 * 8 + kss) * 16 + q0) * 34 + b0v];
                s1 += sP[((m1 * 8 + kss) * 16 + q1) * 34 + b0v];
            }
            sG[r0 * 33 + b0v] = s0;
            sG[r1 * 33 + b0v] = s1;
        }
        __syncthreads();

        // ---- fused LSTM epilogue ----
        if (tid < 256) {
            float gate[4];
#pragma unroll
            for (int g = 0; g < 4; g++) {
                int r = g * 8 + euu;
                gate[g] = sG[r * 33 + eb] + sBias[r] + gx[g];
            }
            float sf = 1.f / (1.f + __expf(-gate[0]));
            float si = 1.f / (1.f + __expf(-gate[1]));
            float so = 1.f / (1.f + __expf(-gate[3]));
            float cn = sf * c_reg + si * tanhf(gate[2]);
            float hn = so * tanhf(cn);
            c_reg = cn;

            __half h16 = __float2half_rn(hn);
            int hp = (t + 1) & 1;
            g_hb[layer][hp][eb * 1024 + u0 + euu] = h16;
            size_t oidx = ((size_t)(eb * Sq + t)) * Hq + u0 + euu;
            if (layer == 0) g_A16h[oidx] = h16;     // fp16 history for layer-1 GEMM
            else            dout[oidx]  = hn;       // final outputs fp32
            if (t == Sq - 1) {
                int su = (u0 + euu) * Bq + eb;
                g_htf[layer][su] = hn;
                g_cst[layer][su] = cn;
            }
            // prefetch next step's input-side gates (hidden behind the barrier)
            if (t + 1 < Sq) {
                size_t gb = gx_base + (size_t)(t + 1) * NG;
#pragma unroll
                for (int g = 0; g < 4; g++) gx[g] = __ldcg(&g_Gx[gb + (size_t)g * 1024]);
            }
        }

        // ---- grid barrier ----
        __threadfence();
        __syncthreads();
        if (tid == 0) {
            atomicAdd(&g_bar[layer], 1u);
            unsigned target = (unsigned)NB * (unsigned)(t + 1);
            while (*(volatile unsigned*)&g_bar[layer] < target) { }
        }
        __syncthreads();
    }
}

// ---------------------------------------------------------------------------
// Tail: h_n [L,B,H] then c_n [L,B,H] after outputs.
// ---------------------------------------------------------------------------
__global__ void k_final(float* __restrict__ out) {
    int i = blockIdx.x * blockDim.x + threadIdx.x;
    int n = 2 * Bq * Hq;
    if (i < n) {
        int l = i / (Bq * Hq);
        int r = i - l * (Bq * Hq);
        int b = r / Hq;
        int u = r - b * Hq;
        out[(size_t)Mq * Hq + i]     = g_htf[l][u * Bq + b];
        out[(size_t)Mq * Hq + n + i] = g_cst[l][u * Bq + b];
    }
}

// ---------------------------------------------------------------------------
extern "C" void kernel_launch(void* const* d_in, const int* in_sizes, int n_in,
                              void* d_out, int out_size) {
    const float* x   = (const float*)d_in[0];
    const float* Wx0 = (const float*)d_in[1];
    const float* Wh0 = (const float*)d_in[2];
    const float* bx0 = (const float*)d_in[3];
    const float* bh0 = (const float*)d_in[4];
    const float* Wx1 = (const float*)d_in[5];
    const float* Wh1 = (const float*)d_in[6];
    const float* bx1 = (const float*)d_in[7];
    const float* bh1 = (const float*)d_in[8];
    float* out = (float*)d_out;

    cudaFuncSetAttribute(k_gemm_mma,  cudaFuncAttributeMaxDynamicSharedMemorySize, GSMEM_BYTES);
    cudaFuncSetAttribute(k_recur_mma, cudaFuncAttributeMaxDynamicSharedMemorySize, RSMEM_BYTES);

    static __half *pA16x = nullptr, *pA16h = nullptr, *pW16h = nullptr, *pW16l = nullptr, *pFh = nullptr;
    if (!pA16x) {
        cudaGetSymbolAddress((void**)&pA16x, g_A16x);
        cudaGetSymbolAddress((void**)&pA16h, g_A16h);
        cudaGetSymbolAddress((void**)&pW16h, g_W16h);
        cudaGetSymbolAddress((void**)&pW16l, g_W16l);
        cudaGetSymbolAddress((void**)&pFh,   g_Fh);
    }

    const int nZ = 2 * 2 * Bq * 1024 / 2;
    k_zero_state<<<(nZ + 255) / 256, 256>>>();

    const int nA4 = Mq * 1024 / 4;
    const int nW4 = NG * 1024 / 4;
    dim3 ggrid(NG / 128, Mq / 128);      // (32, 128)

    // Layer 0
    k_tof16<<<(nA4 + 255) / 256, 256>>>(x, pA16x, nA4);
    k_split_f16<<<(nW4 + 255) / 256, 256>>>(Wx0, pW16h, pW16l, nW4);
    k_gemm_mma<<<ggrid, 256, GSMEM_BYTES>>>(pA16x);
    k_tof16<<<(nW4 + 255) / 256, 256>>>(Wh0, pFh, nW4);
    k_recur_mma<<<NB, RNT, RSMEM_BYTES>>>(bx0, bh0, out, 0);

    // Layer 1 (A = fp16 h history written by layer-0 recurrence)
    k_split_f16<<<(nW4 + 255) / 256, 256>>>(Wx1, pW16h, pW16l, nW4);
    k_gemm_mma<<<ggrid, 256, GSMEM_BYTES>>>(pA16h);
    k_tof16<<<(nW4 + 255) / 256, 256>>>(Wh1, pFh, nW4);
    k_recur_mma<<<NB, RNT, RSMEM_BYTES>>>(bx1, bh1, out, 1);

    // Tail
    if (out_size >= Mq * Hq + 4 * Bq * Hq)
        k_final<<<(2 * Bq * Hq + 255) / 256, 256>>>(out);
}

// round 10
// speedup vs baseline: 6.5194x; 1.1776x over previous
#include <cuda_runtime.h>
#include <cuda_fp16.h>
#include <math.h>
#include <stdint.h>

// Problem constants
#define Bq 32
#define Sq 512
#define Dq 1024
#define Hq 1024
#define NG 4096            // 4*H
#define Mq (Bq * Sq)       // 16384
#define HPAD 1032          // halves per smem h-tile row (1024 + 8)
#define FPHASES 513        // wavefront phases (L0: 0..511, L1: 1..512)

// ---------------------------------------------------------------------------
// Scratch (device globals -- no allocations allowed)
// ---------------------------------------------------------------------------
static __device__ float g_Gx[(size_t)Mq * NG];             // layer-0 input-side gates
static __device__ float g_htf[2][Hq * Bq];                 // final h [layer][u*32+b]
static __device__ float g_cst[2][Hq * Bq];                 // final c [layer][u*32+b]
static __device__ unsigned g_bar[1];                       // grid barrier counter
static __device__ __half g_A16x[(size_t)Mq * 1024];        // x fp16 (GEMM A)
static __device__ __half g_W16h[(size_t)NG * 1024];        // GEMM Wx0 hi
static __device__ __half g_W16l[(size_t)NG * 1024];        // GEMM Wx0 lo
static __device__ __half g_F0[(size_t)NG * 1024];          // Wh0 fp16
static __device__ __half g_F1[(size_t)NG * 1024];          // Wh1 fp16
static __device__ __half g_X1[(size_t)NG * 1024];          // Wx1 fp16 (1-term)
static __device__ __half g_h0[2][Bq * 1024];               // layer-0 h exchange [parity][b][k]
static __device__ __half g_h1[2][Bq * 1024];               // layer-1 h exchange

// ---------------------------------------------------------------------------
// Base-ISA tensor helpers
// ---------------------------------------------------------------------------
__device__ __forceinline__ uint32_t smem_to_u32(const void* p) {
    uint32_t a;
    asm("{ .reg .u64 t; cvta.to.shared.u64 t, %1; cvt.u32.u64 %0, t; }" : "=r"(a) : "l"(p));
    return a;
}

#define LDSM_X4(r, addr) \
    asm volatile("ldmatrix.sync.aligned.m8n8.x4.shared.b16 {%0,%1,%2,%3}, [%4];" \
        : "=r"((r)[0]), "=r"((r)[1]), "=r"((r)[2]), "=r"((r)[3]) : "r"(addr))

#define MMA16816_FP(d, a, b0, b1) \
    asm volatile("mma.sync.aligned.m16n8k16.row.col.f32.f16.f16.f32 " \
        "{%0,%1,%2,%3}, {%4,%5,%6,%7}, {%8,%9}, {%0,%1,%2,%3};" \
        : "+f"((d)[0]), "+f"((d)[1]), "+f"((d)[2]), "+f"((d)[3]) \
        : "r"((a)[0]), "r"((a)[1]), "r"((a)[2]), "r"((a)[3]), "r"(b0), "r"(b1))

#define CP_ASYNC16(saddr, gptr) \
    asm volatile("cp.async.cg.shared.global [%0], [%1], 16;" :: "r"(saddr), "l"(gptr))
#define CP_COMMIT() asm volatile("cp.async.commit_group;" ::: "memory")
#define CP_WAIT(n)  asm volatile("cp.async.wait_group %0;" :: "n"(n) : "memory")

// ---------------------------------------------------------------------------
// Zero fp16 h state + barrier counter
// ---------------------------------------------------------------------------
__global__ void k_zero_state() {
    int i = blockIdx.x * blockDim.x + threadIdx.x;
    int n = 2 * Bq * 1024 / 2;               // u32 per layer array
    if (i < n) {
        ((uint32_t*)g_h0)[i] = 0u;
        ((uint32_t*)g_h1)[i] = 0u;
    }
    if (i == 0) g_bar[0] = 0u;
}

// ---------------------------------------------------------------------------
// fp32 -> fp16 single (rn)
// ---------------------------------------------------------------------------
__global__ void k_tof16(const float* __restrict__ src, __half* __restrict__ dst, int n4) {
    int i = blockIdx.x * blockDim.x + threadIdx.x;
    if (i >= n4) return;
    float4 v = ((const float4*)src)[i];
    ((__half2*)dst)[i * 2 + 0] = __halves2half2(__float2half_rn(v.x), __float2half_rn(v.y));
    ((__half2*)dst)[i * 2 + 1] = __halves2half2(__float2half_rn(v.z), __float2half_rn(v.w));
}

// ---------------------------------------------------------------------------
// fp32 -> fp16 (hi, lo) split (GEMM weights)
// ---------------------------------------------------------------------------
__global__ void k_split_f16(const float* __restrict__ src,
                            __half* __restrict__ hi,
                            __half* __restrict__ lo, int n4)
{
    int i = blockIdx.x * blockDim.x + threadIdx.x;
    if (i >= n4) return;
    float4 v = ((const float4*)src)[i];
    __half h0 = __float2half_rn(v.x), h1 = __float2half_rn(v.y);
    __half h2 = __float2half_rn(v.z), h3 = __float2half_rn(v.w);
    __half l0 = __float2half_rn(v.x - __half2float(h0));
    __half l1 = __float2half_rn(v.y - __half2float(h1));
    __half l2 = __float2half_rn(v.z - __half2float(h2));
    __half l3 = __float2half_rn(v.w - __half2float(h3));
    ((__half2*)hi)[i * 2 + 0] = __halves2half2(h0, h1);
    ((__half2*)hi)[i * 2 + 1] = __halves2half2(h2, h3);
    ((__half2*)lo)[i * 2 + 0] = __halves2half2(l0, l1);
    ((__half2*)lo)[i * 2 + 1] = __halves2half2(l2, l3);
}

// ---------------------------------------------------------------------------
// Tensor-core GEMM (fp16, 2-term):  g_Gx = A16x @ (W16h+W16l)^T   (layer 0)
// ---------------------------------------------------------------------------
#define GT_H   (128 * 72)
#define GBUF_BYTES (3 * GT_H * 2)
#define GSMEM_BYTES (2 * GBUF_BYTES)

__global__ __launch_bounds__(256, 1) void k_gemm_mma(const __half* __restrict__ A16)
{
    extern __shared__ __align__(16) char smem[];
    uint32_t sm_base = smem_to_u32(smem);
    int tid = threadIdx.x;
    int bn = blockIdx.x * 128;
    int bm = blockIdx.y * 128;
    int lane = tid & 31;
    int wid = tid >> 5;
    int wm = (wid & 1) * 64;
    int wn = (wid >> 1) * 32;

    const __half* gsrc[3];
    gsrc[0] = A16    + (size_t)bm * 1024;
    gsrc[1] = g_W16h + (size_t)bn * 1024;
    gsrc[2] = g_W16l + (size_t)bn * 1024;

    float acc[4][4][4];
#pragma unroll
    for (int i = 0; i < 4; i++)
#pragma unroll
        for (int j = 0; j < 4; j++)
#pragma unroll
            for (int k = 0; k < 4; k++) acc[i][j][k] = 0.f;

    int row_a = lane & 15;
    int kh_a  = lane >> 4;
    int row_b = (lane & 7) + ((lane >> 4) << 3);
    int kh_b  = (lane >> 3) & 1;

#define ISSUE_CHUNK(ch) do {                                                   \
    int _k0 = (ch) * 64;                                                       \
    uint32_t _sb = sm_base + ((ch) & 1) * GBUF_BYTES;                          \
    _Pragma("unroll")                                                          \
    for (int _r = 0; _r < 12; _r++) {                                          \
        int _id = tid + _r * 256;                                              \
        int _tile = _id >> 10;                                                 \
        int _row = (_id >> 3) & 127;                                           \
        int _k8 = (_id & 7) * 8;                                               \
        CP_ASYNC16(_sb + (uint32_t)(_tile * GT_H + _row * 72 + _k8) * 2,       \
                   gsrc[_tile] + (size_t)_row * 1024 + _k0 + _k8);             \
    }                                                                          \
    CP_COMMIT();                                                               \
} while (0)

    ISSUE_CHUNK(0);

    for (int ch = 0; ch < 16; ch++) {
        if (ch + 1 < 16) { ISSUE_CHUNK(ch + 1); CP_WAIT(1); }
        else             { CP_WAIT(0); }
        __syncthreads();

        uint32_t sb = sm_base + (ch & 1) * GBUF_BYTES;
        uint32_t a_t  = sb;
        uint32_t wh_t = sb + GT_H * 2;
        uint32_t wl_t = sb + 2 * GT_H * 2;

#pragma unroll
        for (int kk = 0; kk < 4; kk++) {
            uint32_t af[4][4], wh[2][4], wl[2][4];
#pragma unroll
            for (int mi = 0; mi < 4; mi++) {
                uint32_t off = (uint32_t)((wm + mi * 16 + row_a) * 72 + kk * 16 + kh_a * 8) * 2;
                LDSM_X4(af[mi], a_t + off);
            }
#pragma unroll
            for (int p = 0; p < 2; p++) {
                uint32_t off = (uint32_t)((wn + p * 16 + row_b) * 72 + kk * 16 + kh_b * 8) * 2;
                LDSM_X4(wh[p], wh_t + off);
                LDSM_X4(wl[p], wl_t + off);
            }
#pragma unroll
            for (int mi = 0; mi < 4; mi++)
#pragma unroll
                for (int ni = 0; ni < 4; ni++) {
                    int pr = ni >> 1, sb2 = (ni & 1) * 2;
                    MMA16816_FP(acc[mi][ni], af[mi], wh[pr][sb2], wh[pr][sb2 + 1]);
                    MMA16816_FP(acc[mi][ni], af[mi], wl[pr][sb2], wl[pr][sb2 + 1]);
                }
        }
        __syncthreads();
    }
#undef ISSUE_CHUNK

    int g = lane >> 2, tig = lane & 3;
#pragma unroll
    for (int mi = 0; mi < 4; mi++) {
#pragma unroll
        for (int ni = 0; ni < 4; ni++) {
            int row = bm + wm + mi * 16 + g;
            int col = bn + wn + ni * 8 + tig * 2;
            float2 v0 = make_float2(acc[mi][ni][0], acc[mi][ni][1]);
            float2 v1 = make_float2(acc[mi][ni][2], acc[mi][ni][3]);
            *(float2*)&g_Gx[(size_t)row * NG + col] = v0;
            *(float2*)&g_Gx[(size_t)(row + 8) * NG + col] = v1;
        }
    }
}

// ---------------------------------------------------------------------------
// Fused wavefront recurrence: both LSTM layers in one persistent kernel.
// 128 CTAs x 512 thr. CTA 0..63 = layer 0 (16 units each), 64..127 = layer 1.
// Phase p: L0 computes h0[p] (p<=511); L1 computes step t=p-1 (p>=1) using
// h0[p-1] (published last phase) + h1[p-2].
//   L0: gates = Gx0[t] + Wh0@h0[t-1]          (Wh0 frags in regs, 64 MMA/warp)
//   L1: gates = Wx1@h0[t] + Wh1@h1[t-1] + b   (Wh1 regs; Wx1 permanent smem)
// Partials k-reduced via smem atomicAdd into sG.
// ---------------------------------------------------------------------------
#define SWX_OFF   66048                       // after sH (32 x 1032 halves)
#define SG_OFF    (SWX_OFF + 131072)          // 197120
#define SBIAS_OFF (SG_OFF + 64 * 33 * 4)      // 205568
#define FSMEM_BYTES (SBIAS_OFF + 256)         // 205824

__global__ __launch_bounds__(512, 1) void k_fused(
    const float* __restrict__ bx0, const float* __restrict__ bh0,
    const float* __restrict__ bx1, const float* __restrict__ bh1,
    float* __restrict__ dout)
{
    extern __shared__ __align__(16) char smem[];
    __half* sH   = (__half*)smem;
    float* sG    = (float*)(smem + SG_OFF);
    float* sBias = (float*)(smem + SBIAS_OFF);
    uint32_t smem_u = smem_to_u32(smem);
    uint32_t sH_u = smem_u;

    int tid = threadIdx.x, lane = tid & 31, wid = tid >> 5;
    int mi = wid & 3, ks = wid >> 2;
    bool L1c = (blockIdx.x >= 64);
    int u0 = (L1c ? blockIdx.x - 64 : blockIdx.x) * 16;

    // ---- prologue: Wh frags (64 rows x 1024, staged in 2 rounds of 32) ----
    uint32_t a_w[16][4];
    {
        const __half* Wsrc = L1c ? g_F1 : g_F0;
        int r = tid >> 4, c16 = tid & 15;
        for (int rd = 0; rd < 2; rd++) {
            int lr = rd * 32 + r;
            int jrow = (lr >> 4) * 1024 + u0 + (lr & 15);
#pragma unroll
            for (int j = 0; j < 8; j++) {
                int cc = c16 + j * 16;
                *(uint4*)(sH + r * HPAD + cc * 8) =
                    __ldcg((const uint4*)(Wsrc + (size_t)jrow * 1024 + cc * 8));
            }
            __syncthreads();
            if ((mi >> 1) == rd) {
                int arow = (mi & 1) * 16 + (lane & 15);
                int acol8 = (lane >> 4) * 8;
                uint32_t ab = sH_u + (uint32_t)(arow * HPAD + acol8) * 2;
#pragma unroll
                for (int kg = 0; kg < 16; kg++)
                    LDSM_X4(a_w[kg], ab + (uint32_t)((ks * 256 + kg * 16) * 2));
            }
            __syncthreads();
        }
    }

    // ---- prologue: L1 loads Wx1 slice into permanent smem (swizzled) ----
    if (L1c) {
        int lr = tid >> 3, c8 = (tid & 7) * 8;
        int jrow = (lr >> 4) * 1024 + u0 + (lr & 15);
        uint32_t rxor = (uint32_t)((lr & 7) << 4);
#pragma unroll
        for (int j = 0; j < 16; j++) {
            int c = c8 + j * 64;
            uint4 v = __ldcg((const uint4*)(g_X1 + (size_t)jrow * 1024 + c));
            uint32_t off = (uint32_t)(lr * 2048) + (((uint32_t)(c * 2)) ^ rxor);
            *(uint4*)(smem + SWX_OFF + off) = v;
        }
    }
    if (tid < 64) {
        int jrow = (tid >> 4) * 1024 + u0 + (tid & 15);
        sBias[tid] = L1c ? (bx1[jrow] + bh1[jrow]) : (bx0[jrow] + bh0[jrow]);
    }
    __syncthreads();

    // ---- B-frag lane addressing (h tile [32][HPAD]) ----
    int brow = ((lane >> 4) * 8) + (lane & 7);
    int bcol8 = ((lane >> 3) & 1) * 8;
    uint32_t bb0 = sH_u + (uint32_t)(brow * HPAD + bcol8) * 2;
    uint32_t bb2 = bb0 + (uint32_t)(16 * HPAD) * 2;

    // Wx frag lane addressing (sWX, swizzled, row stride 2048B)
    int wrow = mi * 16 + (lane & 15);
    uint32_t wxbase = smem_u + SWX_OFF + (uint32_t)(wrow * 2048);
    uint32_t wxxor = (uint32_t)((wrow & 7) << 4);
    uint32_t wxk0 = (uint32_t)((ks * 256 + (lane >> 4) * 8) * 2);

    // epilogue / staging ids
    int eb = tid >> 4, euu = tid & 15;         // (batch, unit) -- 512 cells
    int hb = tid >> 4, hc = tid & 15;          // h staging
    float c_reg = 0.f;

    size_t gx_base = ((size_t)(eb * Sq)) * NG + u0 + euu;
    float gx[4];
    if (!L1c) {
#pragma unroll
        for (int g = 0; g < 4; g++) gx[g] = __ldcg(&g_Gx[gx_base + (size_t)g * 1024]);
    }

    for (int p = 0; p < FPHASES; p++) {
        bool act = L1c ? (p >= 1) : (p <= 511);
        if (act) {
            int t = L1c ? (p - 1) : p;
            float acc[4][4];
#pragma unroll
            for (int nf = 0; nf < 4; nf++)
#pragma unroll
                for (int e = 0; e < 4; e++) acc[nf][e] = 0.f;

            // ---- stage h0 tile (both layers read g_h0[p&1]) + zero sG ----
            {
                const __half* src = g_h0[p & 1] + hb * 1024;
                uint32_t dh = sH_u + (uint32_t)(hb * HPAD) * 2;
#pragma unroll
                for (int j = 0; j < 8; j++) {
                    int cc = (hc + j * 16) * 8;
                    CP_ASYNC16(dh + (uint32_t)cc * 2, src + cc);
                }
                CP_COMMIT();
                for (int i = tid; i < 64 * 33; i += 512) sG[i] = 0.f;
                CP_WAIT(0);
            }
            __syncthreads();

            if (L1c) {
                // Wx1 @ h0[t]
#pragma unroll
                for (int kg = 0; kg < 16; kg++) {
                    uint32_t ko = (uint32_t)(ks * 512 + kg * 32);
                    uint32_t bh[8], wf[4];
                    LDSM_X4(&bh[0], bb0 + ko);
                    LDSM_X4(&bh[4], bb2 + ko);
                    LDSM_X4(wf, wxbase + ((wxk0 + (uint32_t)(kg * 32)) ^ wxxor));
#pragma unroll
                    for (int nf = 0; nf < 4; nf++)
                        MMA16816_FP(acc[nf], wf, bh[nf * 2], bh[nf * 2 + 1]);
                }
                __syncthreads();
                // stage h1[t-1]
                {
                    const __half* src = g_h1[t & 1] + hb * 1024;
                    uint32_t dh = sH_u + (uint32_t)(hb * HPAD) * 2;
#pragma unroll
                    for (int j = 0; j < 8; j++) {
                        int cc = (hc + j * 16) * 8;
                        CP_ASYNC16(dh + (uint32_t)cc * 2, src + cc);
                    }
                    CP_COMMIT();
                    CP_WAIT(0);
                }
                __syncthreads();
                // Wh1 @ h1[t-1]
#pragma unroll
                for (int kg = 0; kg < 16; kg++) {
                    uint32_t ko = (uint32_t)(ks * 512 + kg * 32);
                    uint32_t bh[8];
                    LDSM_X4(&bh[0], bb0 + ko);
                    LDSM_X4(&bh[4], bb2 + ko);
#pragma unroll
                    for (int nf = 0; nf < 4; nf++)
                        MMA16816_FP(acc[nf], a_w[kg], bh[nf * 2], bh[nf * 2 + 1]);
                }
            } else {
                // Wh0 @ h0[t-1]
#pragma unroll
                for (int kg = 0; kg < 16; kg++) {
                    uint32_t ko = (uint32_t)(ks * 512 + kg * 32);
                    uint32_t bh[8];
                    LDSM_X4(&bh[0], bb0 + ko);
                    LDSM_X4(&bh[4], bb2 + ko);
#pragma unroll
                    for (int nf = 0; nf < 4; nf++)
                        MMA16816_FP(acc[nf], a_w[kg], bh[nf * 2], bh[nf * 2 + 1]);
                }
            }

            // ---- k-reduce via smem atomics ----
            {
                int r16 = lane >> 2, cl = (lane & 3) * 2;
#pragma unroll
                for (int nf = 0; nf < 4; nf++) {
#pragma unroll
                    for (int e = 0; e < 4; e++) {
                        int row = mi * 16 + r16 + ((e & 2) ? 8 : 0);
                        int b   = nf * 8 + cl + (e & 1);
                        atomicAdd(&sG[row * 33 + b], acc[nf][e]);
                    }
                }
            }
            __syncthreads();

            // ---- fused LSTM epilogue (512 cells: (eb, u0+euu)) ----
            {
                float gate[4];
#pragma unroll
                for (int g = 0; g < 4; g++) {
                    gate[g] = sG[(g * 16 + euu) * 33 + eb] + sBias[g * 16 + euu];
                    if (!L1c) gate[g] += gx[g];
                }
                float sf = 1.f / (1.f + __expf(-gate[0]));
                float si = 1.f / (1.f + __expf(-gate[1]));
                float so = 1.f / (1.f + __expf(-gate[3]));
                float cn = sf * c_reg + si * tanhf(gate[2]);
                float hn = so * tanhf(cn);
                c_reg = cn;
                __half h16 = __float2half_rn(hn);

                if (L1c) {
                    dout[((size_t)(eb * Sq + t)) * Hq + u0 + euu] = hn;
                    g_h1[(t + 1) & 1][eb * 1024 + u0 + euu] = h16;
                    if (t == Sq - 1) {
                        int su = (u0 + euu) * Bq + eb;
                        g_htf[1][su] = hn; g_cst[1][su] = cn;
                    }
                } else {
                    g_h0[(t + 1) & 1][eb * 1024 + u0 + euu] = h16;
                    if (t == Sq - 1) {
                        int su = (u0 + euu) * Bq + eb;
                        g_htf[0][su] = hn; g_cst[0][su] = cn;
                    }
                    if (t + 1 < Sq) {
                        size_t gb = gx_base + (size_t)(t + 1) * NG;
#pragma unroll
                        for (int g = 0; g < 4; g++) gx[g] = __ldcg(&g_Gx[gb + (size_t)g * 1024]);
                    }
                }
            }
        }

        // ---- grid barrier (all 128 CTAs, every phase) ----
        __threadfence();
        __syncthreads();
        if (tid == 0) {
            atomicAdd(&g_bar[0], 1u);
            unsigned target = 128u * (unsigned)(p + 1);
            while (*(volatile unsigned*)&g_bar[0] < target) { }
        }
        __syncthreads();
    }
}

// ---------------------------------------------------------------------------
// Tail: h_n [L,B,H] then c_n [L,B,H] after outputs.
// ---------------------------------------------------------------------------
__global__ void k_final(float* __restrict__ out) {
    int i = blockIdx.x * blockDim.x + threadIdx.x;
    int n = 2 * Bq * Hq;
    if (i < n) {
        int l = i / (Bq * Hq);
        int r = i - l * (Bq * Hq);
        int b = r / Hq;
        int u = r - b * Hq;
        out[(size_t)Mq * Hq + i]     = g_htf[l][u * Bq + b];
        out[(size_t)Mq * Hq + n + i] = g_cst[l][u * Bq + b];
    }
}

// ---------------------------------------------------------------------------
extern "C" void kernel_launch(void* const* d_in, const int* in_sizes, int n_in,
                              void* d_out, int out_size) {
    const float* x   = (const float*)d_in[0];
    const float* Wx0 = (const float*)d_in[1];
    const float* Wh0 = (const float*)d_in[2];
    const float* bx0 = (const float*)d_in[3];
    const float* bh0 = (const float*)d_in[4];
    const float* Wx1 = (const float*)d_in[5];
    const float* Wh1 = (const float*)d_in[6];
    const float* bx1 = (const float*)d_in[7];
    const float* bh1 = (const float*)d_in[8];
    float* out = (float*)d_out;

    cudaFuncSetAttribute(k_gemm_mma, cudaFuncAttributeMaxDynamicSharedMemorySize, GSMEM_BYTES);
    cudaFuncSetAttribute(k_fused,    cudaFuncAttributeMaxDynamicSharedMemorySize, FSMEM_BYTES);

    static __half *pA16x = nullptr, *pW16h = nullptr, *pW16l = nullptr;
    static __half *pF0 = nullptr, *pF1 = nullptr, *pX1 = nullptr;
    if (!pA16x) {
        cudaGetSymbolAddress((void**)&pA16x, g_A16x);
        cudaGetSymbolAddress((void**)&pW16h, g_W16h);
        cudaGetSymbolAddress((void**)&pW16l, g_W16l);
        cudaGetSymbolAddress((void**)&pF0,   g_F0);
        cudaGetSymbolAddress((void**)&pF1,   g_F1);
        cudaGetSymbolAddress((void**)&pX1,   g_X1);
    }

    const int nZ = 2 * Bq * 1024 / 2;
    k_zero_state<<<(nZ + 255) / 256, 256>>>();

    const int nA4 = Mq * 1024 / 4;
    const int nW4 = NG * 1024 / 4;
    dim3 ggrid(NG / 128, Mq / 128);      // (32, 128)

    // Layer-0 input GEMM operands + GEMM
    k_tof16<<<(nA4 + 255) / 256, 256>>>(x, pA16x, nA4);
    k_split_f16<<<(nW4 + 255) / 256, 256>>>(Wx0, pW16h, pW16l, nW4);
    k_gemm_mma<<<ggrid, 256, GSMEM_BYTES>>>(pA16x);

    // Recurrent weights fp16
    k_tof16<<<(nW4 + 255) / 256, 256>>>(Wh0, pF0, nW4);
    k_tof16<<<(nW4 + 255) / 256, 256>>>(Wh1, pF1, nW4);
    k_tof16<<<(nW4 + 255) / 256, 256>>>(Wx1, pX1, nW4);

    // Fused 2-layer wavefront recurrence
    k_fused<<<128, 512, FSMEM_BYTES>>>(bx0, bh0, bx1, bh1, out);

    // Tail
    if (out_size >= Mq * Hq + 4 * Bq * Hq)
        k_final<<<(2 * Bq * Hq + 255) / 256, 256>>>(out);
}

// round 11
// speedup vs baseline: 7.7968x; 1.1959x over previous
#include <cuda_runtime.h>
#include <cuda_fp16.h>
#include <math.h>
#include <stdint.h>

// Problem constants
#define Bq 32
#define Sq 512
#define Hq 1024
#define NG 4096            // 4*H
#define Mq (Bq * Sq)       // 16384
#define HPAD 1032          // halves per smem h-tile row (1024 + 8)
#define FPHASES 514        // wavefront phases (L0 steps 0..511 @p, L1 steps t=p-2)

// ---------------------------------------------------------------------------
// Scratch (device globals -- no allocations allowed)
// ---------------------------------------------------------------------------
static __device__ float g_Gx[(size_t)Mq * NG];             // layer-0 input-side gates
static __device__ float g_xp[2][64][64 * 32];              // Wx1@h0 partial gates [par][cta][row*32+b]
static __device__ float g_htf[2][Hq * Bq];                 // final h [layer][u*32+b]
static __device__ float g_cst[2][Hq * Bq];                 // final c [layer][u*32+b]
static __device__ unsigned g_bar[1];                       // grid barrier counter
static __device__ __half g_A16x[(size_t)Mq * 1024];        // x fp16 (GEMM A)
static __device__ __half g_W16h[(size_t)NG * 1024];        // GEMM Wx0 hi
static __device__ __half g_W16l[(size_t)NG * 1024];        // GEMM Wx0 lo
static __device__ __half g_F0[(size_t)NG * 1024];          // Wh0 fp16
static __device__ __half g_F1[(size_t)NG * 1024];          // Wh1 fp16
static __device__ __half g_X1[(size_t)NG * 1024];          // Wx1 fp16 (1-term)
static __device__ __half g_h0[2][Bq * 1024];               // layer-0 h exchange [parity][b][k]
static __device__ __half g_h1[2][Bq * 1024];               // layer-1 h exchange

// ---------------------------------------------------------------------------
// Base-ISA tensor helpers
// ---------------------------------------------------------------------------
__device__ __forceinline__ uint32_t smem_to_u32(const void* p) {
    uint32_t a;
    asm("{ .reg .u64 t; cvta.to.shared.u64 t, %1; cvt.u32.u64 %0, t; }" : "=r"(a) : "l"(p));
    return a;
}

#define LDSM_X4(r, addr) \
    asm volatile("ldmatrix.sync.aligned.m8n8.x4.shared.b16 {%0,%1,%2,%3}, [%4];" \
        : "=r"((r)[0]), "=r"((r)[1]), "=r"((r)[2]), "=r"((r)[3]) : "r"(addr))

#define MMA16816_FP(d, a, b0, b1) \
    asm volatile("mma.sync.aligned.m16n8k16.row.col.f32.f16.f16.f32 " \
        "{%0,%1,%2,%3}, {%4,%5,%6,%7}, {%8,%9}, {%0,%1,%2,%3};" \
        : "+f"((d)[0]), "+f"((d)[1]), "+f"((d)[2]), "+f"((d)[3]) \
        : "r"((a)[0]), "r"((a)[1]), "r"((a)[2]), "r"((a)[3]), "r"(b0), "r"(b1))

#define CP_ASYNC16(saddr, gptr) \
    asm volatile("cp.async.cg.shared.global [%0], [%1], 16;" :: "r"(saddr), "l"(gptr))
#define CP_COMMIT() asm volatile("cp.async.commit_group;" ::: "memory")
#define CP_WAIT(n)  asm volatile("cp.async.wait_group %0;" :: "n"(n) : "memory")

// ---------------------------------------------------------------------------
// Zero fp16 h state + barrier counter
// ---------------------------------------------------------------------------
__global__ void k_zero_state() {
    int i = blockIdx.x * blockDim.x + threadIdx.x;
    int n = 2 * Bq * 1024 / 2;               // u32 per layer array
    if (i < n) {
        ((uint32_t*)g_h0)[i] = 0u;
        ((uint32_t*)g_h1)[i] = 0u;
    }
    if (i == 0) g_bar[0] = 0u;
}

// ---------------------------------------------------------------------------
// fp32 -> fp16 single (rn)
// ---------------------------------------------------------------------------
__global__ void k_tof16(const float* __restrict__ src, __half* __restrict__ dst, int n4) {
    int i = blockIdx.x * blockDim.x + threadIdx.x;
    if (i >= n4) return;
    float4 v = ((const float4*)src)[i];
    ((__half2*)dst)[i * 2 + 0] = __halves2half2(__float2half_rn(v.x), __float2half_rn(v.y));
    ((__half2*)dst)[i * 2 + 1] = __halves2half2(__float2half_rn(v.z), __float2half_rn(v.w));
}

// ---------------------------------------------------------------------------
// fp32 -> fp16 (hi, lo) split (GEMM weights)
// ---------------------------------------------------------------------------
__global__ void k_split_f16(const float* __restrict__ src,
                            __half* __restrict__ hi,
                            __half* __restrict__ lo, int n4)
{
    int i = blockIdx.x * blockDim.x + threadIdx.x;
    if (i >= n4) return;
    float4 v = ((const float4*)src)[i];
    __half h0 = __float2half_rn(v.x), h1 = __float2half_rn(v.y);
    __half h2 = __float2half_rn(v.z), h3 = __float2half_rn(v.w);
    __half l0 = __float2half_rn(v.x - __half2float(h0));
    __half l1 = __float2half_rn(v.y - __half2float(h1));
    __half l2 = __float2half_rn(v.z - __half2float(h2));
    __half l3 = __float2half_rn(v.w - __half2float(h3));
    ((__half2*)hi)[i * 2 + 0] = __halves2half2(h0, h1);
    ((__half2*)hi)[i * 2 + 1] = __halves2half2(h2, h3);
    ((__half2*)lo)[i * 2 + 0] = __halves2half2(l0, l1);
    ((__half2*)lo)[i * 2 + 1] = __halves2half2(l2, l3);
}

// ---------------------------------------------------------------------------
// Tensor-core GEMM (fp16, 2-term):  g_Gx = A16x @ (W16h+W16l)^T   (layer 0)
// ---------------------------------------------------------------------------
#define GT_H   (128 * 72)
#define GBUF_BYTES (3 * GT_H * 2)
#define GSMEM_BYTES (2 * GBUF_BYTES)

__global__ __launch_bounds__(256, 1) void k_gemm_mma(const __half* __restrict__ A16)
{
    extern __shared__ __align__(16) char smem[];
    uint32_t sm_base = smem_to_u32(smem);
    int tid = threadIdx.x;
    int bn = blockIdx.x * 128;
    int bm = blockIdx.y * 128;
    int lane = tid & 31;
    int wid = tid >> 5;
    int wm = (wid & 1) * 64;
    int wn = (wid >> 1) * 32;

    const __half* gsrc[3];
    gsrc[0] = A16    + (size_t)bm * 1024;
    gsrc[1] = g_W16h + (size_t)bn * 1024;
    gsrc[2] = g_W16l + (size_t)bn * 1024;

    float acc[4][4][4];
#pragma unroll
    for (int i = 0; i < 4; i++)
#pragma unroll
        for (int j = 0; j < 4; j++)
#pragma unroll
            for (int k = 0; k < 4; k++) acc[i][j][k] = 0.f;

    int row_a = lane & 15;
    int kh_a  = lane >> 4;
    int row_b = (lane & 7) + ((lane >> 4) << 3);
    int kh_b  = (lane >> 3) & 1;

#define ISSUE_CHUNK(ch) do {                                                   \
    int _k0 = (ch) * 64;                                                       \
    uint32_t _sb = sm_base + ((ch) & 1) * GBUF_BYTES;                          \
    _Pragma("unroll")                                                          \
    for (int _r = 0; _r < 12; _r++) {                                          \
        int _id = tid + _r * 256;                                              \
        int _tile = _id >> 10;                                                 \
        int _row = (_id >> 3) & 127;                                           \
        int _k8 = (_id & 7) * 8;                                               \
        CP_ASYNC16(_sb + (uint32_t)(_tile * GT_H + _row * 72 + _k8) * 2,       \
                   gsrc[_tile] + (size_t)_row * 1024 + _k0 + _k8);             \
    }                                                                          \
    CP_COMMIT();                                                               \
} while (0)

    ISSUE_CHUNK(0);

    for (int ch = 0; ch < 16; ch++) {
        if (ch + 1 < 16) { ISSUE_CHUNK(ch + 1); CP_WAIT(1); }
        else             { CP_WAIT(0); }
        __syncthreads();

        uint32_t sb = sm_base + (ch & 1) * GBUF_BYTES;
        uint32_t a_t  = sb;
        uint32_t wh_t = sb + GT_H * 2;
        uint32_t wl_t = sb + 2 * GT_H * 2;

#pragma unroll
        for (int kk = 0; kk < 4; kk++) {
            uint32_t af[4][4], wh[2][4], wl[2][4];
#pragma unroll
            for (int mi = 0; mi < 4; mi++) {
                uint32_t off = (uint32_t)((wm + mi * 16 + row_a) * 72 + kk * 16 + kh_a * 8) * 2;
                LDSM_X4(af[mi], a_t + off);
            }
#pragma unroll
            for (int p = 0; p < 2; p++) {
                uint32_t off = (uint32_t)((wn + p * 16 + row_b) * 72 + kk * 16 + kh_b * 8) * 2;
                LDSM_X4(wh[p], wh_t + off);
                LDSM_X4(wl[p], wl_t + off);
            }
#pragma unroll
            for (int mi = 0; mi < 4; mi++)
#pragma unroll
                for (int ni = 0; ni < 4; ni++) {
                    int pr = ni >> 1, sb2 = (ni & 1) * 2;
                    MMA16816_FP(acc[mi][ni], af[mi], wh[pr][sb2], wh[pr][sb2 + 1]);
                    MMA16816_FP(acc[mi][ni], af[mi], wl[pr][sb2], wl[pr][sb2 + 1]);
                }
        }
        __syncthreads();
    }
#undef ISSUE_CHUNK

    int g = lane >> 2, tig = lane & 3;
#pragma unroll
    for (int mi = 0; mi < 4; mi++) {
#pragma unroll
        for (int ni = 0; ni < 4; ni++) {
            int row = bm + wm + mi * 16 + g;
            int col = bn + wn + ni * 8 + tig * 2;
            float2 v0 = make_float2(acc[mi][ni][0], acc[mi][ni][1]);
            float2 v1 = make_float2(acc[mi][ni][2], acc[mi][ni][3]);
            *(float2*)&g_Gx[(size_t)row * NG + col] = v0;
            *(float2*)&g_Gx[(size_t)(row + 8) * NG + col] = v1;
        }
    }
}

// ---------------------------------------------------------------------------
// Fused wavefront recurrence (rebalanced, wavefront depth 2):
// CTA 0..63 = L0 (16 units each), CTA 64..127 = L1 (16 units each).
// Phase p:
//   L0 (p<=511): step t=p.  gates = Gx0[t] + Wh0@h0[t-1].
//   L0 (1<=p<=512): ALSO computes xp[p-1] = Wx1_slice@h0[p-1] (h already
//       staged), reduced and stored to g_xp -- Wx1 slice resident in smem.
//   L1 (2<=p<=513): step t=p-2. gates = xp[t] (from global) + Wh1@h1[t-1].
// Partials in sP[4ks][64][34]; epilogue reads sP directly (no atomics).
// ---------------------------------------------------------------------------
#define SP_STRIDE 34
#define SP_KS (64 * SP_STRIDE)                 // floats per ks-slice
#define SWX_OFF   66048                        // after sH (32 x 1032 halves)
#define SP_OFF    (SWX_OFF + 131072)           // 197120
#define SBIAS_OFF (SP_OFF + 4 * SP_KS * 4)     // 231936
#define FSMEM_BYTES (SBIAS_OFF + 256)          // 232192 (<= 232448 max)

__global__ __launch_bounds__(512, 1) void k_fused(
    const float* __restrict__ bx0, const float* __restrict__ bh0,
    const float* __restrict__ bx1, const float* __restrict__ bh1,
    float* __restrict__ dout)
{
    extern __shared__ __align__(16) char smem[];
    __half* sH   = (__half*)smem;
    float* sP    = (float*)(smem + SP_OFF);
    float* sBias = (float*)(smem + SBIAS_OFF);
    uint32_t smem_u = smem_to_u32(smem);
    uint32_t sH_u = smem_u;

    int tid = threadIdx.x, lane = tid & 31, wid = tid >> 5;
    int mi = wid & 3, ks = wid >> 2;
    bool L0c = (blockIdx.x < 64);
    int cta = L0c ? blockIdx.x : (blockIdx.x - 64);
    int u0 = cta * 16;

    // ---- prologue: Wh frags (64 rows x 1024, staged in 2 rounds of 32) ----
    uint32_t a_w[16][4];
    {
        const __half* Wsrc = L0c ? g_F0 : g_F1;
        int r = tid >> 4, c16 = tid & 15;
        for (int rd = 0; rd < 2; rd++) {
            int lr = rd * 32 + r;
            int jrow = (lr >> 4) * 1024 + u0 + (lr & 15);
#pragma unroll
            for (int j = 0; j < 8; j++) {
                int cc = c16 + j * 16;
                *(uint4*)(sH + r * HPAD + cc * 8) =
                    __ldcg((const uint4*)(Wsrc + (size_t)jrow * 1024 + cc * 8));
            }
            __syncthreads();
            if ((mi >> 1) == rd) {
                int arow = (mi & 1) * 16 + (lane & 15);
                int acol8 = (lane >> 4) * 8;
                uint32_t ab = sH_u + (uint32_t)(arow * HPAD + acol8) * 2;
#pragma unroll
                for (int kg = 0; kg < 16; kg++)
                    LDSM_X4(a_w[kg], ab + (uint32_t)((ks * 256 + kg * 16) * 2));
            }
            __syncthreads();
        }
    }

    // ---- prologue: L0 CTAs load Wx1 slice into permanent smem (swizzled) ----
    if (L0c) {
        int lr = tid >> 3, c8 = (tid & 7) * 8;
        int jrow = (lr >> 4) * 1024 + u0 + (lr & 15);
        uint32_t rxor = (uint32_t)((lr & 7) << 4);
#pragma unroll
        for (int j = 0; j < 16; j++) {
            int c = c8 + j * 64;
            uint4 v = __ldcg((const uint4*)(g_X1 + (size_t)jrow * 1024 + c));
            uint32_t off = (uint32_t)(lr * 2048) + (((uint32_t)(c * 2)) ^ rxor);
            *(uint4*)(smem + SWX_OFF + off) = v;
        }
    }
    if (tid < 64) {
        int jrow = (tid >> 4) * 1024 + u0 + (tid & 15);
        sBias[tid] = L0c ? (bx0[jrow] + bh0[jrow]) : (bx1[jrow] + bh1[jrow]);
    }
    __syncthreads();

    // ---- B-frag lane addressing (h tile [32][HPAD]) ----
    int brow = ((lane >> 4) * 8) + (lane & 7);
    int bcol8 = ((lane >> 3) & 1) * 8;
    uint32_t bb0 = sH_u + (uint32_t)(brow * HPAD + bcol8) * 2;
    uint32_t bb2 = bb0 + (uint32_t)(16 * HPAD) * 2;

    // Wx1 frag lane addressing (sWX, swizzled, row stride 2048B)
    int wrow = mi * 16 + (lane & 15);
    uint32_t wxbase = smem_u + SWX_OFF + (uint32_t)(wrow * 2048);
    uint32_t wxxor = (uint32_t)((wrow & 7) << 4);
    uint32_t wxk0 = (uint32_t)((ks * 256 + (lane >> 4) * 8) * 2);

    // epilogue / staging ids
    int eb = tid >> 4, euu = tid & 15;
    int hb = tid >> 4, hc = tid & 15;
    float c_reg = 0.f;

    size_t gx_base = ((size_t)(eb * Sq)) * NG + u0 + euu;
    float gx[4];
    if (L0c) {
#pragma unroll
        for (int g = 0; g < 4; g++) gx[g] = __ldcg(&g_Gx[gx_base + (size_t)g * 1024]);
    }

    // partials write addressing
    int pr16 = lane >> 2, pcolb = (lane & 3) * 2;

    for (int p = 0; p < FPHASES; p++) {
        int t = L0c ? p : (p - 2);
        bool doStep  = L0c ? (p <= 511) : (p >= 2 && p <= 513);
        bool doStage = L0c ? (p <= 512) : doStep;
        bool doXP    = L0c && (p >= 1 && p <= 512);

        float xq[4];
        // ---- slot A: stage h tile + (L1) prefetch xp ----
        if (doStage) {
            const __half* src = (L0c ? g_h0[p & 1] : g_h1[t & 1]) + hb * 1024;
            uint32_t dh = sH_u + (uint32_t)(hb * HPAD) * 2;
#pragma unroll
            for (int j = 0; j < 8; j++) {
                int cc = (hc + j * 16) * 8;
                CP_ASYNC16(dh + (uint32_t)cc * 2, src + cc);
            }
            CP_COMMIT();
            CP_WAIT(0);
        }
        if (!L0c && doStep) {
#pragma unroll
            for (int g = 0; g < 4; g++)
                xq[g] = __ldcg(&g_xp[t & 1][cta][(g * 16 + euu) * 32 + eb]);
        }
        __syncthreads();

        // ---- slot B: pass-1 MMA (L0: Wh0@h0; L1: Wh1@h1) ----
        if (doStep) {
            float acc[4][4];
#pragma unroll
            for (int nf = 0; nf < 4; nf++)
#pragma unroll
                for (int e = 0; e < 4; e++) acc[nf][e] = 0.f;
#pragma unroll
            for (int kg = 0; kg < 16; kg++) {
                uint32_t ko = (uint32_t)(ks * 512 + kg * 32);
                uint32_t bh[8];
                LDSM_X4(&bh[0], bb0 + ko);
                LDSM_X4(&bh[4], bb2 + ko);
#pragma unroll
                for (int nf = 0; nf < 4; nf++)
                    MMA16816_FP(acc[nf], a_w[kg], bh[nf * 2], bh[nf * 2 + 1]);
            }
            float* base = sP + ks * SP_KS + (mi * 16) * SP_STRIDE;
#pragma unroll
            for (int nf = 0; nf < 4; nf++) {
                *(float2*)&base[(pr16)     * SP_STRIDE + nf * 8 + pcolb] = make_float2(acc[nf][0], acc[nf][1]);
                *(float2*)&base[(pr16 + 8) * SP_STRIDE + nf * 8 + pcolb] = make_float2(acc[nf][2], acc[nf][3]);
            }
        }
        __syncthreads();

        // ---- slot C: LSTM epilogue (reads sP directly, conflict-free) ----
        if (doStep) {
            float gate[4];
#pragma unroll
            for (int g = 0; g < 4; g++) {
                float s = 0.f;
#pragma unroll
                for (int kss = 0; kss < 4; kss++)
                    s += sP[kss * SP_KS + (g * 16 + euu) * SP_STRIDE + eb];
                gate[g] = s + sBias[g * 16 + euu] + (L0c ? gx[g] : xq[g]);
            }
            float sf = 1.f / (1.f + __expf(-gate[0]));
            float si = 1.f / (1.f + __expf(-gate[1]));
            float so = 1.f / (1.f + __expf(-gate[3]));
            float cn = sf * c_reg + si * tanhf(gate[2]);
            float hn = so * tanhf(cn);
            c_reg = cn;
            __half h16 = __float2half_rn(hn);

            if (L0c) {
                g_h0[(t + 1) & 1][eb * 1024 + u0 + euu] = h16;
                if (t == Sq - 1) {
                    int su = (u0 + euu) * Bq + eb;
                    g_htf[0][su] = hn; g_cst[0][su] = cn;
                }
                if (t + 1 < Sq) {
                    size_t gb = gx_base + (size_t)(t + 1) * NG;
#pragma unroll
                    for (int g = 0; g < 4; g++) gx[g] = __ldcg(&g_Gx[gb + (size_t)g * 1024]);
                }
            } else {
                dout[((size_t)(eb * Sq + t)) * Hq + u0 + euu] = hn;
                g_h1[(t + 1) & 1][eb * 1024 + u0 + euu] = h16;
                if (t == Sq - 1) {
                    int su = (u0 + euu) * Bq + eb;
                    g_htf[1][su] = hn; g_cst[1][su] = cn;
                }
            }
        }
        __syncthreads();

        // ---- slot D: L0 pass B -- Wx1 @ h0 (staged tile reused) ----
        if (doXP) {
            float acc[4][4];
#pragma unroll
            for (int nf = 0; nf < 4; nf++)
#pragma unroll
                for (int e = 0; e < 4; e++) acc[nf][e] = 0.f;
#pragma unroll
            for (int kg = 0; kg < 16; kg++) {
                uint32_t ko = (uint32_t)(ks * 512 + kg * 32);
                uint32_t bh[8], wf[4];
                LDSM_X4(&bh[0], bb0 + ko);
                LDSM_X4(&bh[4], bb2 + ko);
                LDSM_X4(wf, wxbase + ((wxk0 + (uint32_t)(kg * 32)) ^ wxxor));
#pragma unroll
                for (int nf = 0; nf < 4; nf++)
                    MMA16816_FP(acc[nf], wf, bh[nf * 2], bh[nf * 2 + 1]);
            }
            float* base = sP + ks * SP_KS + (mi * 16) * SP_STRIDE;
#pragma unroll
            for (int nf = 0; nf < 4; nf++) {
                *(float2*)&base[(pr16)     * SP_STRIDE + nf * 8 + pcolb] = make_float2(acc[nf][0], acc[nf][1]);
                *(float2*)&base[(pr16 + 8) * SP_STRIDE + nf * 8 + pcolb] = make_float2(acc[nf][2], acc[nf][3]);
            }
        }
        __syncthreads();

        // ---- slot E: reduce pass-B partials, store xp[p-1] ----
        if (doXP) {
            int par = (p - 1) & 1;
#pragma unroll
            for (int i = 0; i < 4; i++) {
                int o = tid + i * 512;
                int row = o >> 5, b = o & 31;
                float s = 0.f;
#pragma unroll
                for (int kss = 0; kss < 4; kss++)
                    s += sP[kss * SP_KS + row * SP_STRIDE + b];
                g_xp[par][cta][row * 32 + b] = s;
            }
        }

        // ---- grid barrier (all 128 CTAs, every phase) ----
        __threadfence();
        __syncthreads();
        if (tid == 0) {
            atomicAdd(&g_bar[0], 1u);
            unsigned target = 128u * (unsigned)(p + 1);
            while (*(volatile unsigned*)&g_bar[0] < target) { }
        }
        __syncthreads();
    }
}

// ---------------------------------------------------------------------------
// Tail: h_n [L,B,H] then c_n [L,B,H] after outputs.
// ---------------------------------------------------------------------------
__global__ void k_final(float* __restrict__ out) {
    int i = blockIdx.x * blockDim.x + threadIdx.x;
    int n = 2 * Bq * Hq;
    if (i < n) {
        int l = i / (Bq * Hq);
        int r = i - l * (Bq * Hq);
        int b = r / Hq;
        int u = r - b * Hq;
        out[(size_t)Mq * Hq + i]     = g_htf[l][u * Bq + b];
        out[(size_t)Mq * Hq + n + i] = g_cst[l][u * Bq + b];
    }
}

// ---------------------------------------------------------------------------
extern "C" void kernel_launch(void* const* d_in, const int* in_sizes, int n_in,
                              void* d_out, int out_size) {
    const float* x   = (const float*)d_in[0];
    const float* Wx0 = (const float*)d_in[1];
    const float* Wh0 = (const float*)d_in[2];
    const float* bx0 = (const float*)d_in[3];
    const float* bh0 = (const float*)d_in[4];
    const float* Wx1 = (const float*)d_in[5];
    const float* Wh1 = (const float*)d_in[6];
    const float* bx1 = (const float*)d_in[7];
    const float* bh1 = (const float*)d_in[8];
    float* out = (float*)d_out;

    cudaFuncSetAttribute(k_gemm_mma, cudaFuncAttributeMaxDynamicSharedMemorySize, GSMEM_BYTES);
    cudaFuncSetAttribute(k_fused,    cudaFuncAttributeMaxDynamicSharedMemorySize, FSMEM_BYTES);

    static __half *pA16x = nullptr, *pW16h = nullptr, *pW16l = nullptr;
    static __half *pF0 = nullptr, *pF1 = nullptr, *pX1 = nullptr;
    if (!pA16x) {
        cudaGetSymbolAddress((void**)&pA16x, g_A16x);
        cudaGetSymbolAddress((void**)&pW16h, g_W16h);
        cudaGetSymbolAddress((void**)&pW16l, g_W16l);
        cudaGetSymbolAddress((void**)&pF0,   g_F0);
        cudaGetSymbolAddress((void**)&pF1,   g_F1);
        cudaGetSymbolAddress((void**)&pX1,   g_X1);
    }

    const int nZ = 2 * Bq * 1024 / 2;
    k_zero_state<<<(nZ + 255) / 256, 256>>>();

    const int nA4 = Mq * 1024 / 4;
    const int nW4 = NG * 1024 / 4;
    dim3 ggrid(NG / 128, Mq / 128);      // (32, 128)

    // Layer-0 input GEMM operands + GEMM
    k_tof16<<<(nA4 + 255) / 256, 256>>>(x, pA16x, nA4);
    k_split_f16<<<(nW4 + 255) / 256, 256>>>(Wx0, pW16h, pW16l, nW4);
    k_gemm_mma<<<ggrid, 256, GSMEM_BYTES>>>(pA16x);

    // Recurrent weights fp16
    k_tof16<<<(nW4 + 255) / 256, 256>>>(Wh0, pF0, nW4);
    k_tof16<<<(nW4 + 255) / 256, 256>>>(Wh1, pF1, nW4);
    k_tof16<<<(nW4 + 255) / 256, 256>>>(Wx1, pX1, nW4);

    // Fused 2-layer wavefront recurrence (rebalanced)
    k_fused<<<128, 512, FSMEM_BYTES>>>(bx0, bh0, bx1, bh1, out);

    // Tail
    if (out_size >= Mq * Hq + 4 * Bq * Hq)
        k_final<<<(2 * Bq * Hq + 255) / 256, 256>>>(out);
}